// round 1
// baseline (speedup 1.0000x reference)
#include <cuda_runtime.h>
#include <math.h>

// Problem constants
#define BT   128          // B*T
#define NP   256          // patches
#define DV   1024         // D_VISION
#define NHD  16           // N_BRANCHES * N_HEADS
#define NBR  4
#define DB   256          // D_BRANCH
#define SCALE 0.125f      // HEAD_DIM^-0.5 = 64^-0.5

// -------- device scratch (no allocation allowed) --------
__device__ float g_wqg[NHD * DV];          // scale * gamma[d] * (Wk[n] @ q[n,h])[d]
__device__ float g_gw [NHD];               // scale * sum_d gamma[d]*wq
__device__ float g_scb[NHD];               // scale * (sum_d beta[d]*wq + bk.q)
__device__ float g_y  [(size_t)NHD * BT * DV];   // y[nh][bt][d]  (8 MB)
__device__ float g_pooled[NBR * BT * DB];  // pooled[n][bt][256]
__device__ float g_sims[BT * 6];           // per-bt pairwise cosine sims

// =============================================================
// Kernel A: fold query into Wk (+ layernorm affine folding)
// grid 16 (nh), 256 threads
// =============================================================
__global__ void prep_kernel(const float* __restrict__ Wk,
                            const float* __restrict__ query,
                            const float* __restrict__ bk,
                            const float* __restrict__ gamma,
                            const float* __restrict__ beta) {
    const int nh = blockIdx.x;
    const int n = nh >> 2, h = nh & 3;
    __shared__ float q_s[64];
    __shared__ float r1[256], r2[256];
    const int t = threadIdx.x;
    if (t < 64) q_s[t] = query[(n * 4 + h) * 64 + t];
    __syncthreads();

    float gw_part = 0.f, bw_part = 0.f;
    const float4* qq = (const float4*)q_s;
    for (int d = t; d < DV; d += 256) {
        const float4* w4 = (const float4*)(Wk + ((size_t)(n * DV + d)) * DB + h * 64);
        float s = 0.f;
        #pragma unroll
        for (int j = 0; j < 16; j++) {
            float4 a = w4[j]; float4 b = qq[j];
            s += a.x * b.x + a.y * b.y + a.z * b.z + a.w * b.w;
        }
        g_wqg[nh * DV + d] = SCALE * gamma[d] * s;
        gw_part += gamma[d] * s;
        bw_part += beta[d] * s;
    }
    r1[t] = gw_part; r2[t] = bw_part;
    __syncthreads();
    for (int s = 128; s; s >>= 1) {
        if (t < s) { r1[t] += r1[t + s]; r2[t] += r2[t + s]; }
        __syncthreads();
    }
    if (t == 0) {
        float bq = 0.f;
        for (int j = 0; j < 64; j++) bq += bk[n * DB + h * 64 + j] * q_s[j];
        g_gw[nh]  = SCALE * r1[0];
        g_scb[nh] = SCALE * (r2[0] + bq);
    }
}

// =============================================================
// Kernel B: per-(b,t) main kernel. grid 128, 256 threads (8 warps)
// pass1: LN stats + scores (from raw input), softmax, diversity partials
// pass2: y[nh][d] = sum_p attn*x_norm  (via folded affine)
// =============================================================
#define SMEM_B_FLOATS (32*1024 + 256 + 256 + 16*256 + 16*256 + 4*256 + 16 + 16)
#define SMEM_B_BYTES  (SMEM_B_FLOATS * 4)

__global__ void __launch_bounds__(256, 1)
main_kernel(const float* __restrict__ frame,
            const float* __restrict__ gamma,
            const float* __restrict__ beta) {
    extern __shared__ float sm[];
    float* xs   = sm;                    // 32 patches x 1024
    float* mu   = xs + 32 * 1024;        // 256
    float* rsig = mu + 256;              // 256
    float* sc   = rsig + 256;            // 16 x 256 (scores -> attn)
    float* ar   = sc + 16 * 256;         // 16 x 256 (attn * rsig)
    float* av   = ar + 16 * 256;         // 4 x 256 (attn_avg)
    float* cnh  = av + 4 * 256;          // 16
    float* avn  = cnh + 16;              // 4 (inv norms)

    const int t = threadIdx.x;
    const int w = t >> 5, lane = t & 31;
    const int bt = blockIdx.x;
    const float4* frame4 = (const float4*)(frame + (size_t)bt * NP * DV);
    float4* xs4v = (float4*)xs;
    const float4* wq4 = (const float4*)g_wqg;

    // per-warp: two (branch,head) rows, weights resident in registers
    const int nh0 = 2 * w, nh1 = 2 * w + 1;
    float4 wA[8], wB[8];
    #pragma unroll
    for (int c = 0; c < 8; c++) {
        wA[c] = wq4[nh0 * 256 + c * 32 + lane];
        wB[c] = wq4[nh1 * 256 + c * 32 + lane];
    }
    const float gw0 = g_gw[nh0], gw1 = g_gw[nh1];
    const float sb0 = g_scb[nh0], sb1 = g_scb[nh1];

    // ---------------- pass 1 ----------------
    for (int kc = 0; kc < 8; kc++) {
        #pragma unroll 4
        for (int i = t; i < 8192; i += 256) xs4v[i] = frame4[kc * 8192 + i];
        __syncthreads();

        // LN stats: warp w handles 4 patches
        #pragma unroll
        for (int r = 0; r < 4; r++) {
            int lp = w + r * 8;
            const float4* row = xs4v + lp * 256;
            float s = 0.f, ss = 0.f;
            #pragma unroll
            for (int c = 0; c < 8; c++) {
                float4 v = row[c * 32 + lane];
                s  += (v.x + v.y) + (v.z + v.w);
                ss += v.x * v.x + v.y * v.y + v.z * v.z + v.w * v.w;
            }
            #pragma unroll
            for (int o = 16; o; o >>= 1) {
                s  += __shfl_xor_sync(0xffffffffu, s,  o);
                ss += __shfl_xor_sync(0xffffffffu, ss, o);
            }
            if (lane == 0) {
                int p = kc * 32 + lp;
                float m = s * (1.f / 1024.f);
                mu[p] = m;
                rsig[p] = rsqrtf(ss * (1.f / 1024.f) - m * m + 1e-5f);
            }
        }
        __syncthreads();

        // scores: each warp computes its 2 rows over all 32 chunk patches
        for (int lp = 0; lp < 32; lp++) {
            const float4* row = xs4v + lp * 256;
            float d0 = 0.f, d1 = 0.f;
            #pragma unroll
            for (int c = 0; c < 8; c++) {
                float4 v = row[c * 32 + lane];
                d0 += v.x * wA[c].x + v.y * wA[c].y + v.z * wA[c].z + v.w * wA[c].w;
                d1 += v.x * wB[c].x + v.y * wB[c].y + v.z * wB[c].z + v.w * wB[c].w;
            }
            #pragma unroll
            for (int o = 16; o; o >>= 1) {
                d0 += __shfl_xor_sync(0xffffffffu, d0, o);
                d1 += __shfl_xor_sync(0xffffffffu, d1, o);
            }
            if (lane == 0) {
                int p = kc * 32 + lp;
                float r = rsig[p], rm = rsig[p] * mu[p];
                sc[nh0 * 256 + p] = r * d0 - rm * gw0 + sb0;
                sc[nh1 * 256 + p] = r * d1 - rm * gw1 + sb1;
            }
        }
        __syncthreads();
    }

    // ---------------- softmax (warp w: rows 2w, 2w+1) ----------------
    #pragma unroll
    for (int rr = 0; rr < 2; rr++) {
        int row = 2 * w + rr;
        float* srow = sc + row * 256;
        float vals[8];
        float mx = -1e30f;
        #pragma unroll
        for (int i = 0; i < 8; i++) { vals[i] = srow[i * 32 + lane]; mx = fmaxf(mx, vals[i]); }
        #pragma unroll
        for (int o = 16; o; o >>= 1) mx = fmaxf(mx, __shfl_xor_sync(0xffffffffu, mx, o));
        float s = 0.f;
        #pragma unroll
        for (int i = 0; i < 8; i++) { vals[i] = __expf(vals[i] - mx); s += vals[i]; }
        #pragma unroll
        for (int o = 16; o; o >>= 1) s += __shfl_xor_sync(0xffffffffu, s, o);
        float inv = 1.f / s;
        float cp = 0.f;
        #pragma unroll
        for (int i = 0; i < 8; i++) {
            int p = i * 32 + lane;
            float a = vals[i] * inv;
            float arv = a * rsig[p];
            srow[p] = a;                // keep attn for attn_avg
            ar[row * 256 + p] = arv;
            cp += arv * mu[p];
        }
        #pragma unroll
        for (int o = 16; o; o >>= 1) cp += __shfl_xor_sync(0xffffffffu, cp, o);
        if (lane == 0) cnh[row] = cp;
    }
    __syncthreads();

    // ---------------- diversity partials ----------------
    if (w < 4) {
        int n = w;
        float nrm = 0.f;
        #pragma unroll
        for (int i = 0; i < 8; i++) {
            int p = i * 32 + lane;
            float aa = 0.25f * (sc[(4 * n + 0) * 256 + p] + sc[(4 * n + 1) * 256 + p] +
                                sc[(4 * n + 2) * 256 + p] + sc[(4 * n + 3) * 256 + p]);
            av[n * 256 + p] = aa;
            nrm += aa * aa;
        }
        #pragma unroll
        for (int o = 16; o; o >>= 1) nrm += __shfl_xor_sync(0xffffffffu, nrm, o);
        if (lane == 0) avn[n] = 1.f / fmaxf(sqrtf(nrm), 1e-8f);
    }
    __syncthreads();
    if (w < 6) {
        const int pi[6] = {0, 0, 0, 1, 1, 2};
        const int pj[6] = {1, 2, 3, 2, 3, 3};
        int i = pi[w], j = pj[w];
        float dt = 0.f;
        #pragma unroll
        for (int c = 0; c < 8; c++) {
            int p = c * 32 + lane;
            dt += av[i * 256 + p] * av[j * 256 + p];
        }
        #pragma unroll
        for (int o = 16; o; o >>= 1) dt += __shfl_xor_sync(0xffffffffu, dt, o);
        if (lane == 0) g_sims[bt * 6 + w] = dt * avn[i] * avn[j];
    }
    __syncthreads();

    // ---------------- pass 2: y accumulation ----------------
    float4 yacc[16];
    #pragma unroll
    for (int nh = 0; nh < 16; nh++) yacc[nh] = make_float4(0.f, 0.f, 0.f, 0.f);

    for (int kc = 0; kc < 8; kc++) {
        #pragma unroll 4
        for (int i = t; i < 8192; i += 256) xs4v[i] = frame4[kc * 8192 + i];
        __syncthreads();
        for (int lp = 0; lp < 32; lp++) {
            float4 xv = xs4v[lp * 256 + t];
            const float* arp = ar + (kc * 32 + lp);
            #pragma unroll
            for (int nh = 0; nh < 16; nh++) {
                float a = arp[nh * 256];
                yacc[nh].x += a * xv.x; yacc[nh].y += a * xv.y;
                yacc[nh].z += a * xv.z; yacc[nh].w += a * xv.w;
            }
        }
        __syncthreads();
    }

    float4 g4 = ((const float4*)gamma)[t];
    float4 b4 = ((const float4*)beta)[t];
    #pragma unroll
    for (int nh = 0; nh < 16; nh++) {
        float cc = cnh[nh];
        float4 o;
        o.x = g4.x * (yacc[nh].x - cc) + b4.x;
        o.y = g4.y * (yacc[nh].y - cc) + b4.y;
        o.z = g4.z * (yacc[nh].z - cc) + b4.z;
        o.w = g4.w * (yacc[nh].w - cc) + b4.w;
        ((float4*)(g_y + ((size_t)(nh * BT + bt)) * DV))[t] = o;
    }
}

// =============================================================
// Kernel C: pooled[nh][bt][64] = y[nh][bt] @ Wv[n][:, h*64:h*64+64] + bv
// grid (16 nh, 8 bt-tiles of 16), 256 threads
// =============================================================
__global__ void __launch_bounds__(256, 1)
pooled_kernel(const float* __restrict__ Wv, const float* __restrict__ bv) {
    const int nh = blockIdx.x, btile = blockIdx.y;
    const int n = nh >> 2, h = nh & 3;
    __shared__ float4 wv_s[64 * 16];   // [k 64][j4 16]
    __shared__ float  ys[16 * 64];     // [bt 16][k 64]
    const int t = threadIdx.x;
    const int btl = t >> 4, jq = t & 15;
    float4 acc = make_float4(0.f, 0.f, 0.f, 0.f);

    for (int kc = 0; kc < 16; kc++) {
        for (int i = t; i < 1024; i += 256) {
            int d = i >> 4, q = i & 15;
            wv_s[i] = ((const float4*)(Wv + ((size_t)(n * DV + kc * 64 + d)) * DB + h * 64))[q];
        }
        {
            int bb = t >> 4, kq = t & 15;
            ((float4*)ys)[t] =
                ((const float4*)(g_y + ((size_t)(nh * BT + btile * 16 + bb)) * DV + kc * 64))[kq];
        }
        __syncthreads();
        #pragma unroll 8
        for (int kk = 0; kk < 64; kk++) {
            float yv = ys[btl * 64 + kk];
            float4 wv = wv_s[kk * 16 + jq];
            acc.x += yv * wv.x; acc.y += yv * wv.y;
            acc.z += yv * wv.z; acc.w += yv * wv.w;
        }
        __syncthreads();
    }
    float4 bvv = ((const float4*)(bv + n * DB + h * 64))[jq];
    acc.x += bvv.x; acc.y += bvv.y; acc.z += bvv.z; acc.w += bvv.w;
    ((float4*)(g_pooled + ((size_t)(n * BT + btile * 16 + btl)) * DB + h * 64))[jq] = acc;
}

// =============================================================
// Kernel D: out[n][bt][:] = pooled[n][bt] @ Wo[n] + bo, written transposed
// into streams layout d_out[(bt*4 + n)*256 + m].  grid (4, 8), 256 threads
// =============================================================
__global__ void __launch_bounds__(256, 1)
out_kernel(const float* __restrict__ Wo, const float* __restrict__ bo,
           float* __restrict__ out) {
    const int n = blockIdx.x, btile = blockIdx.y;
    __shared__ float ps[16 * 256];   // pooled tile
    __shared__ float ws[16 * 256];   // Wo k-chunk
    const int t = threadIdx.x;
    for (int i = t; i < 1024; i += 256)
        ((float4*)ps)[i] = ((const float4*)(g_pooled + ((size_t)(n * BT + btile * 16)) * DB))[i];

    const int btl = t >> 4, mq = t & 15;
    float acc[16];
    #pragma unroll
    for (int i = 0; i < 16; i++) acc[i] = 0.f;

    for (int kc = 0; kc < 16; kc++) {
        __syncthreads();
        for (int i = t; i < 1024; i += 256)
            ((float4*)ws)[i] = ((const float4*)(Wo + ((size_t)(n * DB + kc * 16)) * DB))[i];
        __syncthreads();
        for (int k = 0; k < 16; k++) {
            float pv = ps[btl * 256 + kc * 16 + k];
            #pragma unroll
            for (int m4 = 0; m4 < 4; m4++) {
                float4 wv = ((float4*)ws)[k * 64 + mq * 4 + m4];
                acc[m4 * 4 + 0] += pv * wv.x;
                acc[m4 * 4 + 1] += pv * wv.y;
                acc[m4 * 4 + 2] += pv * wv.z;
                acc[m4 * 4 + 3] += pv * wv.w;
            }
        }
    }
    const int btg = btile * 16 + btl;
    const float* bon = bo + n * DB + mq * 16;
    float* dst = out + ((size_t)btg * 4 + n) * DB + mq * 16;
    #pragma unroll
    for (int m4 = 0; m4 < 4; m4++) {
        float4 o;
        o.x = acc[m4 * 4 + 0] + bon[m4 * 4 + 0];
        o.y = acc[m4 * 4 + 1] + bon[m4 * 4 + 1];
        o.z = acc[m4 * 4 + 2] + bon[m4 * 4 + 2];
        o.w = acc[m4 * 4 + 3] + bon[m4 * 4 + 3];
        ((float4*)dst)[m4] = o;
    }
}

// =============================================================
// Kernel E: diversity loss finalize (deterministic fixed-order sum)
// =============================================================
__global__ void loss_kernel(float* __restrict__ out) {
    __shared__ float part[6];
    const int t = threadIdx.x;
    if (t < 6) {
        float s = 0.f;
        for (int b = 0; b < BT; b++) s += g_sims[b * 6 + t];
        part[t] = s;
    }
    __syncthreads();
    if (t == 0) {
        float tot = part[0] + part[1] + part[2] + part[3] + part[4] + part[5];
        out[0] = 0.1f * (tot * (1.f / 128.f)) * (1.f / 6.f);
    }
}

// =============================================================
extern "C" void kernel_launch(void* const* d_in, const int* in_sizes, int n_in,
                              void* d_out, int out_size) {
    const float* frame = (const float*)d_in[0];
    const float* gam   = (const float*)d_in[1];
    const float* bet   = (const float*)d_in[2];
    const float* query = (const float*)d_in[3];
    const float* Wk    = (const float*)d_in[4];
    const float* bk    = (const float*)d_in[5];
    const float* Wv    = (const float*)d_in[6];
    const float* bv    = (const float*)d_in[7];
    const float* Wo    = (const float*)d_in[8];
    const float* bo    = (const float*)d_in[9];
    float* out = (float*)d_out;

    prep_kernel<<<16, 256>>>(Wk, query, bk, gam, bet);

    cudaFuncSetAttribute(main_kernel, cudaFuncAttributeMaxDynamicSharedMemorySize,
                         SMEM_B_BYTES);
    main_kernel<<<128, 256, SMEM_B_BYTES>>>(frame, gam, bet);

    pooled_kernel<<<dim3(16, 8), 256>>>(Wv, bv);
    out_kernel<<<dim3(4, 8), 256>>>(Wo, bo, out);

    if (out_size > BT * NBR * DB)          // streams (131072) then scalar loss
        loss_kernel<<<1, 32>>>(out + (size_t)BT * NBR * DB);
}

// round 2
// speedup vs baseline: 1.6361x; 1.6361x over previous
#include <cuda_runtime.h>
#include <math.h>
#include <stdint.h>

// Problem constants
#define BT   128          // B*T
#define NP   256          // patches
#define DV   1024         // D_VISION
#define NHD  16           // N_BRANCHES * N_HEADS
#define NBR  4
#define DB   256          // D_BRANCH
#define SCALE 0.125f      // HEAD_DIM^-0.5

#define CH    16          // patches per chunk
#define NCH   16          // chunks per bt
#define CHBYTES (CH * DV * 4)   // 65536

typedef unsigned long long u64;

// -------- device scratch (no allocation allowed) --------
__device__ __align__(16) float g_wqg[NHD * DV];
__device__ float g_gw [NHD];
__device__ float g_scb[NHD];
__device__ __align__(16) float g_y[(size_t)NHD * BT * DV];   // 8 MB
__device__ __align__(16) float g_pooled[NBR * BT * DB];
__device__ float g_sims[BT * 6];

// ---------------- f32x2 helpers ----------------
__device__ __forceinline__ u64 fma2(u64 a, u64 b, u64 c) {
    u64 d;
    asm("fma.rn.f32x2 %0, %1, %2, %3;" : "=l"(d) : "l"(a), "l"(b), "l"(c));
    return d;
}
__device__ __forceinline__ u64 mul2(u64 a, u64 b) {
    u64 d;
    asm("mul.rn.f32x2 %0, %1, %2;" : "=l"(d) : "l"(a), "l"(b));
    return d;
}
__device__ __forceinline__ u64 dup2(float v) {
    u64 r;
    asm("mov.b64 %0, {%1, %1};" : "=l"(r) : "f"(v));
    return r;
}
__device__ __forceinline__ u64 pack2(float lo, float hi) {
    u64 r;
    asm("mov.b64 %0, {%1, %2};" : "=l"(r) : "f"(lo), "f"(hi));
    return r;
}
__device__ __forceinline__ void unpack2(u64 v, float& lo, float& hi) {
    asm("mov.b64 {%0, %1}, %2;" : "=f"(lo), "=f"(hi) : "l"(v));
}

// ---------------- mbarrier / bulk-copy helpers ----------------
__device__ __forceinline__ uint32_t smem_u32(const void* p) {
    uint32_t a;
    asm("{ .reg .u64 t; cvta.to.shared.u64 t, %1; cvt.u32.u64 %0, t; }"
        : "=r"(a) : "l"(p));
    return a;
}
__device__ __forceinline__ void mbar_init(uint32_t mbar, uint32_t count) {
    asm volatile("mbarrier.init.shared.b64 [%0], %1;" :: "r"(mbar), "r"(count) : "memory");
}
__device__ __forceinline__ void mbar_expect(uint32_t mbar, uint32_t bytes) {
    asm volatile("mbarrier.arrive.expect_tx.shared.b64 _, [%0], %1;"
                 :: "r"(mbar), "r"(bytes) : "memory");
}
__device__ __forceinline__ void mbar_wait(uint32_t mbar, int phase) {
    asm volatile(
        "{\n\t.reg .pred P;\n\t"
        "WL_%=:\n\t"
        "mbarrier.try_wait.parity.acquire.cta.shared::cta.b64 P, [%0], %1, 0x989680;\n\t"
        "@P bra.uni WD_%=;\n\t"
        "bra.uni WL_%=;\n\t"
        "WD_%=:\n\t}"
        :: "r"(mbar), "r"(phase) : "memory");
}
__device__ __forceinline__ void bulk_g2s(uint32_t dst, const void* src,
                                         uint32_t bytes, uint32_t mbar) {
    asm volatile(
        "cp.async.bulk.shared::cluster.global.mbarrier::complete_tx::bytes [%0], [%1], %2, [%3];"
        :: "r"(dst), "l"(src), "r"(bytes), "r"(mbar) : "memory");
}

// =============================================================
// Kernel A: fold query into Wk (+ layernorm affine folding)
// =============================================================
__global__ void prep_kernel(const float* __restrict__ Wk,
                            const float* __restrict__ query,
                            const float* __restrict__ bk,
                            const float* __restrict__ gamma,
                            const float* __restrict__ beta) {
    const int nh = blockIdx.x;
    const int n = nh >> 2, h = nh & 3;
    __shared__ float q_s[64];
    __shared__ float r1[256], r2[256];
    const int t = threadIdx.x;
    if (t < 64) q_s[t] = query[(n * 4 + h) * 64 + t];
    __syncthreads();

    float gw_part = 0.f, bw_part = 0.f;
    const float4* qq = (const float4*)q_s;
    for (int d = t; d < DV; d += 256) {
        const float4* w4 = (const float4*)(Wk + ((size_t)(n * DV + d)) * DB + h * 64);
        float s = 0.f;
        #pragma unroll
        for (int j = 0; j < 16; j++) {
            float4 a = w4[j]; float4 b = qq[j];
            s += a.x * b.x + a.y * b.y + a.z * b.z + a.w * b.w;
        }
        g_wqg[nh * DV + d] = SCALE * gamma[d] * s;
        gw_part += gamma[d] * s;
        bw_part += beta[d] * s;
    }
    r1[t] = gw_part; r2[t] = bw_part;
    __syncthreads();
    for (int s = 128; s; s >>= 1) {
        if (t < s) { r1[t] += r1[t + s]; r2[t] += r2[t + s]; }
        __syncthreads();
    }
    if (t == 0) {
        float bq = 0.f;
        for (int j = 0; j < 64; j++) bq += bk[n * DB + h * 64 + j] * q_s[j];
        g_gw[nh]  = SCALE * r1[0];
        g_scb[nh] = SCALE * (r2[0] + bq);
    }
}

// =============================================================
// Kernel B: single-pass main kernel (online softmax, f32x2 FMA,
// cp.async.bulk double-buffered chunk loads). grid 128, 256 thr.
// =============================================================
// smem layout (floats):
//  [0..3]      mbar[2] (u64 each)
//  [4..19]     f2s (8 float2)
//  [20..35]    mrow
//  [36..51]    invsr
//  [52..67]    ccrow
//  [68..71]    avn
//  [128..383]  mu
//  [384..639]  rsig
//  [640..895]  ar2c (16 p x 8 pairs, float2)
//  [896..1919] av (4 x 256)
//  [1920..6015] sc (16 x 256 raw scores)
//  [6016..38783] buf (2 x 16 x 1024)
#define SMEM_MAIN_FLOATS 38784
#define SMEM_MAIN_BYTES  (SMEM_MAIN_FLOATS * 4)

__global__ void __launch_bounds__(256, 1)
main_kernel(const float* __restrict__ frame,
            const float* __restrict__ gamma,
            const float* __restrict__ beta) {
    extern __shared__ float smf[];
    float* f2s   = smf + 4;
    float* mrow  = smf + 20;
    float* invsr = smf + 36;
    float* ccrow = smf + 52;
    float* avn   = smf + 68;
    float* mu    = smf + 128;
    float* rsig  = smf + 384;
    float* ar2c  = smf + 640;
    float* av    = smf + 896;
    float* sc    = smf + 1920;
    float* buf   = smf + 6016;

    const int t = threadIdx.x, w = t >> 5, lane = t & 31;
    const int bt = blockIdx.x;
    const uint32_t sbase = smem_u32(smf);
    const uint32_t mbar0 = sbase, mbar1 = sbase + 8;
    const uint32_t bufu = smem_u32(buf);

    const int nh0 = 2 * w, nh1 = nh0 + 1;

    // persistent folded-query weights (f32x2), 2 rows per warp
    u64 wA[16], wB[16];
    {
        const ulonglong2* wa = (const ulonglong2*)(g_wqg + nh0 * DV);
        const ulonglong2* wb = (const ulonglong2*)(g_wqg + nh1 * DV);
        #pragma unroll
        for (int c = 0; c < 8; c++) {
            ulonglong2 va = wa[c * 32 + lane]; wA[2*c] = va.x; wA[2*c+1] = va.y;
            ulonglong2 vb = wb[c * 32 + lane]; wB[2*c] = vb.x; wB[2*c+1] = vb.y;
        }
    }
    const float gw0 = g_gw[nh0], gw1 = g_gw[nh1];
    const float sb0 = g_scb[nh0], sb1 = g_scb[nh1];

    if (t == 0) { mbar_init(mbar0, 1); mbar_init(mbar1, 1); }
    __syncthreads();

    const char* src = (const char*)(frame + (size_t)bt * NP * DV);
    if (t == 0) {
        mbar_expect(mbar0, CHBYTES);
        bulk_g2s(bufu, src, CHBYTES, mbar0);
        mbar_expect(mbar1, CHBYTES);
        bulk_g2s(bufu + CHBYTES, src + CHBYTES, CHBYTES, mbar1);
    }

    u64 yacc[8][4];
    #pragma unroll
    for (int pr = 0; pr < 8; pr++)
        #pragma unroll
        for (int c = 0; c < 4; c++) yacc[pr][c] = 0ull;

    float m0 = -1e30f, m1 = -1e30f, s0 = 0.f, s1 = 0.f, cp0 = 0.f, cp1 = 0.f;

    for (int kc = 0; kc < NCH; kc++) {
        const int b = kc & 1;
        const uint32_t mb = b ? mbar1 : mbar0;
        mbar_wait(mb, (kc >> 1) & 1);
        float* xb = buf + b * (CH * DV);

        // ---- LN stats: warp handles patches 2w, 2w+1 ----
        #pragma unroll
        for (int r = 0; r < 2; r++) {
            const int p = 2 * w + r;
            const float4* row = (const float4*)xb + p * 256;
            float s = 0.f, ss = 0.f;
            #pragma unroll
            for (int c = 0; c < 8; c++) {
                float4 v = row[c * 32 + lane];
                s  += (v.x + v.y) + (v.z + v.w);
                ss += v.x * v.x + v.y * v.y + v.z * v.z + v.w * v.w;
            }
            #pragma unroll
            for (int o = 16; o; o >>= 1) {
                s  += __shfl_xor_sync(0xffffffffu, s,  o);
                ss += __shfl_xor_sync(0xffffffffu, ss, o);
            }
            if (lane == 0) {
                float m = s * (1.f / 1024.f);
                mu[kc * CH + p] = m;
                rsig[kc * CH + p] = rsqrtf(ss * (1.f / 1024.f) - m * m + 1e-5f);
            }
        }
        __syncthreads();

        // ---- scores: warp computes its 2 nh rows over 16 chunk patches ----
        {
            const ulonglong2* x2 = (const ulonglong2*)xb;
            for (int p = 0; p < CH; p++) {
                const ulonglong2* row = x2 + p * 256;
                u64 a0 = 0ull, a1 = 0ull;
                #pragma unroll
                for (int c = 0; c < 8; c++) {
                    ulonglong2 xv = row[c * 32 + lane];
                    a0 = fma2(xv.x, wA[2*c],   a0);
                    a0 = fma2(xv.y, wA[2*c+1], a0);
                    a1 = fma2(xv.x, wB[2*c],   a1);
                    a1 = fma2(xv.y, wB[2*c+1], a1);
                }
                float l0, h0, l1, h1;
                unpack2(a0, l0, h0); unpack2(a1, l1, h1);
                float d0 = l0 + h0, d1 = l1 + h1;
                #pragma unroll
                for (int o = 16; o; o >>= 1) {
                    d0 += __shfl_xor_sync(0xffffffffu, d0, o);
                    d1 += __shfl_xor_sync(0xffffffffu, d1, o);
                }
                if (lane == 0) {
                    float r = rsig[kc * CH + p], q = r * mu[kc * CH + p];
                    sc[nh0 * 256 + kc * CH + p] = fmaf(r, d0, fmaf(-q, gw0, sb0));
                    sc[nh1 * 256 + kc * CH + p] = fmaf(r, d1, fmaf(-q, gw1, sb1));
                }
            }
        }
        __syncthreads();

        // ---- online softmax update (warp w: rows nh0, nh1) ----
        {
            const int pl = lane & 15;
            float v0 = sc[nh0 * 256 + kc * CH + pl];
            float v1 = sc[nh1 * 256 + kc * CH + pl];
            if (lane >= 16) { v0 = -1e30f; v1 = -1e30f; }
            float c0 = v0, c1 = v1;
            #pragma unroll
            for (int o = 8; o; o >>= 1) {
                c0 = fmaxf(c0, __shfl_xor_sync(0xffffffffu, c0, o));
                c1 = fmaxf(c1, __shfl_xor_sync(0xffffffffu, c1, o));
            }
            float mn0 = fmaxf(m0, c0), mn1 = fmaxf(m1, c1);
            float f0 = __expf(m0 - mn0), f1 = __expf(m1 - mn1);
            float e0 = (lane < 16) ? __expf(v0 - mn0) : 0.f;
            float e1 = (lane < 16) ? __expf(v1 - mn1) : 0.f;
            float rs = rsig[kc * CH + pl], mv = mu[kc * CH + pl];
            float ar0 = e0 * rs, ar1 = e1 * rs;
            float su0 = e0, su1 = e1, cq0 = ar0 * mv, cq1 = ar1 * mv;
            #pragma unroll
            for (int o = 8; o; o >>= 1) {
                su0 += __shfl_xor_sync(0xffffffffu, su0, o);
                su1 += __shfl_xor_sync(0xffffffffu, su1, o);
                cq0 += __shfl_xor_sync(0xffffffffu, cq0, o);
                cq1 += __shfl_xor_sync(0xffffffffu, cq1, o);
            }
            s0 = s0 * f0 + su0;   s1 = s1 * f1 + su1;
            cp0 = cp0 * f0 + cq0; cp1 = cp1 * f1 + cq1;
            m0 = mn0; m1 = mn1;
            if (lane < 16) ((float2*)ar2c)[pl * 8 + w] = make_float2(ar0, ar1);
            if (lane == 0) ((float2*)f2s)[w] = make_float2(f0, f1);
        }
        __syncthreads();

        // ---- yacc rescale + accumulate (thread owns cols 4t..4t+3) ----
        {
            #pragma unroll
            for (int pr = 0; pr < 8; pr++) {
                u64 f2 = ((const u64*)f2s)[pr];
                #pragma unroll
                for (int c = 0; c < 4; c++) yacc[pr][c] = mul2(yacc[pr][c], f2);
            }
            const float4* xs4 = (const float4*)xb;
            for (int lp = 0; lp < CH; lp++) {
                float4 xv = xs4[lp * 256 + t];
                u64 x0 = dup2(xv.x), x1 = dup2(xv.y), x2d = dup2(xv.z), x3 = dup2(xv.w);
                #pragma unroll
                for (int pr = 0; pr < 8; pr++) {
                    u64 a2 = ((const u64*)ar2c)[lp * 8 + pr];
                    yacc[pr][0] = fma2(a2, x0,  yacc[pr][0]);
                    yacc[pr][1] = fma2(a2, x1,  yacc[pr][1]);
                    yacc[pr][2] = fma2(a2, x2d, yacc[pr][2]);
                    yacc[pr][3] = fma2(a2, x3,  yacc[pr][3]);
                }
            }
        }
        __syncthreads();   // buffer b now free for reuse

        if (t == 0 && kc + 2 < NCH) {
            mbar_expect(mb, CHBYTES);
            bulk_g2s(bufu + b * CHBYTES, src + (size_t)(kc + 2) * CHBYTES, CHBYTES, mb);
        }
    }

    // ---- finalize per-row softmax state ----
    if (lane == 0) {
        float is0 = 1.f / s0, is1 = 1.f / s1;
        invsr[nh0] = is0;        invsr[nh1] = is1;
        ccrow[nh0] = cp0 * is0;  ccrow[nh1] = cp1 * is1;
        mrow[nh0] = m0;          mrow[nh1] = m1;
    }
    __syncthreads();

    // ---- epilogue: y = gamma*(yacc/s - cc) + beta, write g_y ----
    {
        float4 g4 = ((const float4*)gamma)[t];
        float4 b4 = ((const float4*)beta)[t];
        u64 gd[4] = { dup2(g4.x), dup2(g4.y), dup2(g4.z), dup2(g4.w) };
        u64 bd[4] = { dup2(b4.x), dup2(b4.y), dup2(b4.z), dup2(b4.w) };
        #pragma unroll
        for (int pr = 0; pr < 8; pr++) {
            u64 is2 = pack2(invsr[2*pr], invsr[2*pr+1]);
            u64 nc2 = pack2(-ccrow[2*pr], -ccrow[2*pr+1]);
            float o0[4], o1[4];
            #pragma unroll
            for (int c = 0; c < 4; c++) {
                u64 a = fma2(yacc[pr][c], is2, nc2);
                u64 o = fma2(a, gd[c], bd[c]);
                unpack2(o, o0[c], o1[c]);
            }
            float4 v0 = make_float4(o0[0], o0[1], o0[2], o0[3]);
            float4 v1 = make_float4(o1[0], o1[1], o1[2], o1[3]);
            ((float4*)(g_y + (size_t)((2*pr)     * BT + bt) * DV))[t] = v0;
            ((float4*)(g_y + (size_t)((2*pr + 1) * BT + bt) * DV))[t] = v1;
        }
    }

    // ---- diversity partials (attn recomputed from raw scores) ----
    if (w < 4) {
        const int n = w;
        float nrm = 0.f;
        #pragma unroll
        for (int i = 0; i < 8; i++) {
            int p = i * 32 + lane;
            float aa = 0.f;
            #pragma unroll
            for (int h = 0; h < 4; h++) {
                int r = 4 * n + h;
                aa += __expf(sc[r * 256 + p] - mrow[r]) * invsr[r];
            }
            aa *= 0.25f;
            av[n * 256 + p] = aa;
            nrm += aa * aa;
        }
        #pragma unroll
        for (int o = 16; o; o >>= 1) nrm += __shfl_xor_sync(0xffffffffu, nrm, o);
        if (lane == 0) avn[n] = 1.f / fmaxf(sqrtf(nrm), 1e-8f);
    }
    __syncthreads();
    if (w < 6) {
        const int pi[6] = {0, 0, 0, 1, 1, 2};
        const int pj[6] = {1, 2, 3, 2, 3, 3};
        int i = pi[w], j = pj[w];
        float dt = 0.f;
        #pragma unroll
        for (int c = 0; c < 8; c++) {
            int p = c * 32 + lane;
            dt += av[i * 256 + p] * av[j * 256 + p];
        }
        #pragma unroll
        for (int o = 16; o; o >>= 1) dt += __shfl_xor_sync(0xffffffffu, dt, o);
        if (lane == 0) g_sims[bt * 6 + w] = dt * avn[i] * avn[j];
    }
}

// =============================================================
// Kernel C: pooled[nh][bt][64] = y[nh][bt] @ Wv[n][:, h*64:+64] + bv
// =============================================================
__global__ void __launch_bounds__(256, 1)
pooled_kernel(const float* __restrict__ Wv, const float* __restrict__ bv) {
    const int nh = blockIdx.x, btile = blockIdx.y;
    const int n = nh >> 2, h = nh & 3;
    __shared__ float4 wv_s[64 * 16];
    __shared__ float  ys[16 * 64];
    const int t = threadIdx.x;
    const int btl = t >> 4, jq = t & 15;
    float4 acc = make_float4(0.f, 0.f, 0.f, 0.f);

    for (int kc = 0; kc < 16; kc++) {
        for (int i = t; i < 1024; i += 256) {
            int d = i >> 4, q = i & 15;
            wv_s[i] = ((const float4*)(Wv + ((size_t)(n * DV + kc * 64 + d)) * DB + h * 64))[q];
        }
        {
            int bb = t >> 4, kq = t & 15;
            ((float4*)ys)[t] =
                ((const float4*)(g_y + ((size_t)(nh * BT + btile * 16 + bb)) * DV + kc * 64))[kq];
        }
        __syncthreads();
        #pragma unroll 8
        for (int kk = 0; kk < 64; kk++) {
            float yv = ys[btl * 64 + kk];
            float4 wv = wv_s[kk * 16 + jq];
            acc.x += yv * wv.x; acc.y += yv * wv.y;
            acc.z += yv * wv.z; acc.w += yv * wv.w;
        }
        __syncthreads();
    }
    float4 bvv = ((const float4*)(bv + n * DB + h * 64))[jq];
    acc.x += bvv.x; acc.y += bvv.y; acc.z += bvv.z; acc.w += bvv.w;
    ((float4*)(g_pooled + ((size_t)(n * BT + btile * 16 + btl)) * DB + h * 64))[jq] = acc;
}

// =============================================================
// Kernel D: out = pooled @ Wo + bo, transposed write (conflict-free)
// =============================================================
__global__ void __launch_bounds__(256, 1)
out_kernel(const float* __restrict__ Wo, const float* __restrict__ bo,
           float* __restrict__ out) {
    const int n = blockIdx.x, btile = blockIdx.y;
    __shared__ float ps[16 * 256];
    __shared__ float ws[16 * 256];
    const int t = threadIdx.x;
    for (int i = t; i < 1024; i += 256)
        ((float4*)ps)[i] = ((const float4*)(g_pooled + ((size_t)(n * BT + btile * 16)) * DB))[i];

    const int btl = t >> 4, mq = t & 15;
    float acc[16];
    #pragma unroll
    for (int i = 0; i < 16; i++) acc[i] = 0.f;

    for (int kc = 0; kc < 16; kc++) {
        __syncthreads();
        for (int i = t; i < 1024; i += 256)
            ((float4*)ws)[i] = ((const float4*)(Wo + ((size_t)(n * DB + kc * 16)) * DB))[i];
        __syncthreads();
        for (int k = 0; k < 16; k++) {
            float pv = ps[btl * 256 + kc * 16 + k];
            #pragma unroll
            for (int g = 0; g < 4; g++) {
                // lane-contiguous float4 reads: index = k*64 + g*16 + mq
                float4 wv = ((float4*)ws)[k * 64 + g * 16 + mq];
                acc[g * 4 + 0] += pv * wv.x;
                acc[g * 4 + 1] += pv * wv.y;
                acc[g * 4 + 2] += pv * wv.z;
                acc[g * 4 + 3] += pv * wv.w;
            }
        }
    }
    const int btg = btile * 16 + btl;
    #pragma unroll
    for (int g = 0; g < 4; g++) {
        int mbase = g * 64 + mq * 4;
        float4 o;
        o.x = acc[g * 4 + 0] + bo[n * DB + mbase + 0];
        o.y = acc[g * 4 + 1] + bo[n * DB + mbase + 1];
        o.z = acc[g * 4 + 2] + bo[n * DB + mbase + 2];
        o.w = acc[g * 4 + 3] + bo[n * DB + mbase + 3];
        *((float4*)(out + ((size_t)btg * 4 + n) * DB + mbase)) = o;
    }
}

// =============================================================
// Kernel E: diversity loss finalize
// =============================================================
__global__ void loss_kernel(float* __restrict__ out) {
    __shared__ float part[6];
    const int t = threadIdx.x;
    if (t < 6) {
        float s = 0.f;
        for (int b = 0; b < BT; b++) s += g_sims[b * 6 + t];
        part[t] = s;
    }
    __syncthreads();
    if (t == 0) {
        float tot = part[0] + part[1] + part[2] + part[3] + part[4] + part[5];
        out[0] = 0.1f * (tot * (1.f / 128.f)) * (1.f / 6.f);
    }
}

// =============================================================
extern "C" void kernel_launch(void* const* d_in, const int* in_sizes, int n_in,
                              void* d_out, int out_size) {
    const float* frame = (const float*)d_in[0];
    const float* gam   = (const float*)d_in[1];
    const float* bet   = (const float*)d_in[2];
    const float* query = (const float*)d_in[3];
    const float* Wk    = (const float*)d_in[4];
    const float* bk    = (const float*)d_in[5];
    const float* Wv    = (const float*)d_in[6];
    const float* bv    = (const float*)d_in[7];
    const float* Wo    = (const float*)d_in[8];
    const float* bo    = (const float*)d_in[9];
    float* out = (float*)d_out;

    prep_kernel<<<16, 256>>>(Wk, query, bk, gam, bet);

    static int cfg_done = 0;
    if (!cfg_done) {
        cudaFuncSetAttribute(main_kernel, cudaFuncAttributeMaxDynamicSharedMemorySize,
                             SMEM_MAIN_BYTES);
        cfg_done = 1;
    }
    main_kernel<<<128, 256, SMEM_MAIN_BYTES>>>(frame, gam, bet);

    pooled_kernel<<<dim3(16, 8), 256>>>(Wv, bv);
    out_kernel<<<dim3(4, 8), 256>>>(Wo, bo, out);

    if (out_size > BT * NBR * DB)
        loss_kernel<<<1, 32>>>(out + (size_t)BT * NBR * DB);
}

// round 3
// speedup vs baseline: 2.0929x; 1.2792x over previous
#include <cuda_runtime.h>
#include <math.h>
#include <stdint.h>

// Problem constants
#define BT   128          // B*T
#define NP   256          // patches
#define DV   1024         // D_VISION
#define NHD  16           // N_BRANCHES * N_HEADS
#define NBR  4
#define DB   256          // D_BRANCH
#define SCALE 0.125f      // HEAD_DIM^-0.5

#define CH    16          // patches per chunk (main kernel)
#define NCH   16          // chunks per bt
#define CHBYTES (CH * DV * 4)   // 65536

typedef unsigned long long u64;

// -------- device scratch (no allocation allowed) --------
__device__ __align__(16) float g_wqg[NHD * DV];
__device__ float g_gw [NHD];
__device__ float g_scb[NHD];
__device__ __align__(16) float g_y[(size_t)NHD * BT * DV];   // 8 MB
__device__ __align__(16) float g_pooled[NBR * BT * DB];
__device__ float g_sims[BT * 6];

// ---------------- f32x2 helpers ----------------
__device__ __forceinline__ u64 fma2(u64 a, u64 b, u64 c) {
    u64 d;
    asm("fma.rn.f32x2 %0, %1, %2, %3;" : "=l"(d) : "l"(a), "l"(b), "l"(c));
    return d;
}
__device__ __forceinline__ u64 mul2(u64 a, u64 b) {
    u64 d;
    asm("mul.rn.f32x2 %0, %1, %2;" : "=l"(d) : "l"(a), "l"(b));
    return d;
}
__device__ __forceinline__ u64 dup2(float v) {
    u64 r;
    asm("mov.b64 %0, {%1, %1};" : "=l"(r) : "f"(v));
    return r;
}
__device__ __forceinline__ u64 pack2(float lo, float hi) {
    u64 r;
    asm("mov.b64 %0, {%1, %2};" : "=l"(r) : "f"(lo), "f"(hi));
    return r;
}
__device__ __forceinline__ void unpack2(u64 v, float& lo, float& hi) {
    asm("mov.b64 {%0, %1}, %2;" : "=f"(lo), "=f"(hi) : "l"(v));
}

// ---------------- mbarrier / bulk-copy helpers ----------------
__device__ __forceinline__ uint32_t smem_u32(const void* p) {
    uint32_t a;
    asm("{ .reg .u64 t; cvta.to.shared.u64 t, %1; cvt.u32.u64 %0, t; }"
        : "=r"(a) : "l"(p));
    return a;
}
__device__ __forceinline__ void mbar_init(uint32_t mbar, uint32_t count) {
    asm volatile("mbarrier.init.shared.b64 [%0], %1;" :: "r"(mbar), "r"(count) : "memory");
}
__device__ __forceinline__ void mbar_expect(uint32_t mbar, uint32_t bytes) {
    asm volatile("mbarrier.arrive.expect_tx.shared.b64 _, [%0], %1;"
                 :: "r"(mbar), "r"(bytes) : "memory");
}
__device__ __forceinline__ void mbar_wait(uint32_t mbar, int phase) {
    asm volatile(
        "{\n\t.reg .pred P;\n\t"
        "WL_%=:\n\t"
        "mbarrier.try_wait.parity.acquire.cta.shared::cta.b64 P, [%0], %1, 0x989680;\n\t"
        "@P bra.uni WD_%=;\n\t"
        "bra.uni WL_%=;\n\t"
        "WD_%=:\n\t}"
        :: "r"(mbar), "r"(phase) : "memory");
}
__device__ __forceinline__ void bulk_g2s(uint32_t dst, const void* src,
                                         uint32_t bytes, uint32_t mbar) {
    asm volatile(
        "cp.async.bulk.shared::cluster.global.mbarrier::complete_tx::bytes [%0], [%1], %2, [%3];"
        :: "r"(dst), "l"(src), "r"(bytes), "r"(mbar) : "memory");
}

// =============================================================
// Kernel A: fold query into Wk (+ layernorm affine folding)
// =============================================================
__global__ void prep_kernel(const float* __restrict__ Wk,
                            const float* __restrict__ query,
                            const float* __restrict__ bk,
                            const float* __restrict__ gamma,
                            const float* __restrict__ beta) {
    const int nh = blockIdx.x;
    const int n = nh >> 2, h = nh & 3;
    __shared__ float q_s[64];
    __shared__ float r1[256], r2[256];
    const int t = threadIdx.x;
    if (t < 64) q_s[t] = query[(n * 4 + h) * 64 + t];
    __syncthreads();

    float gw_part = 0.f, bw_part = 0.f;
    const float4* qq = (const float4*)q_s;
    for (int d = t; d < DV; d += 256) {
        const float4* w4 = (const float4*)(Wk + ((size_t)(n * DV + d)) * DB + h * 64);
        float s = 0.f;
        #pragma unroll
        for (int j = 0; j < 16; j++) {
            float4 a = w4[j]; float4 b = qq[j];
            s += a.x * b.x + a.y * b.y + a.z * b.z + a.w * b.w;
        }
        g_wqg[nh * DV + d] = SCALE * gamma[d] * s;
        gw_part += gamma[d] * s;
        bw_part += beta[d] * s;
    }
    r1[t] = gw_part; r2[t] = bw_part;
    __syncthreads();
    for (int s = 128; s; s >>= 1) {
        if (t < s) { r1[t] += r1[t + s]; r2[t] += r2[t + s]; }
        __syncthreads();
    }
    if (t == 0) {
        float bq = 0.f;
        for (int j = 0; j < 64; j++) bq += bk[n * DB + h * 64 + j] * q_s[j];
        g_gw[nh]  = SCALE * r1[0];
        g_scb[nh] = SCALE * (r2[0] + bq);
    }
}

// =============================================================
// Kernel B: single-pass main kernel (unchanged from R2)
// =============================================================
#define SMEM_MAIN_FLOATS 38784
#define SMEM_MAIN_BYTES  (SMEM_MAIN_FLOATS * 4)

__global__ void __launch_bounds__(256, 1)
main_kernel(const float* __restrict__ frame,
            const float* __restrict__ gamma,
            const float* __restrict__ beta) {
    extern __shared__ float smf[];
    float* f2s   = smf + 4;
    float* mrow  = smf + 20;
    float* invsr = smf + 36;
    float* ccrow = smf + 52;
    float* avn   = smf + 68;
    float* mu    = smf + 128;
    float* rsig  = smf + 384;
    float* ar2c  = smf + 640;
    float* av    = smf + 896;
    float* sc    = smf + 1920;
    float* buf   = smf + 6016;

    const int t = threadIdx.x, w = t >> 5, lane = t & 31;
    const int bt = blockIdx.x;
    const uint32_t sbase = smem_u32(smf);
    const uint32_t mbar0 = sbase, mbar1 = sbase + 8;
    const uint32_t bufu = smem_u32(buf);

    const int nh0 = 2 * w, nh1 = nh0 + 1;

    u64 wA[16], wB[16];
    {
        const ulonglong2* wa = (const ulonglong2*)(g_wqg + nh0 * DV);
        const ulonglong2* wb = (const ulonglong2*)(g_wqg + nh1 * DV);
        #pragma unroll
        for (int c = 0; c < 8; c++) {
            ulonglong2 va = wa[c * 32 + lane]; wA[2*c] = va.x; wA[2*c+1] = va.y;
            ulonglong2 vb = wb[c * 32 + lane]; wB[2*c] = vb.x; wB[2*c+1] = vb.y;
        }
    }
    const float gw0 = g_gw[nh0], gw1 = g_gw[nh1];
    const float sb0 = g_scb[nh0], sb1 = g_scb[nh1];

    if (t == 0) { mbar_init(mbar0, 1); mbar_init(mbar1, 1); }
    __syncthreads();

    const char* src = (const char*)(frame + (size_t)bt * NP * DV);
    if (t == 0) {
        mbar_expect(mbar0, CHBYTES);
        bulk_g2s(bufu, src, CHBYTES, mbar0);
        mbar_expect(mbar1, CHBYTES);
        bulk_g2s(bufu + CHBYTES, src + CHBYTES, CHBYTES, mbar1);
    }

    u64 yacc[8][4];
    #pragma unroll
    for (int pr = 0; pr < 8; pr++)
        #pragma unroll
        for (int c = 0; c < 4; c++) yacc[pr][c] = 0ull;

    float m0 = -1e30f, m1 = -1e30f, s0 = 0.f, s1 = 0.f, cp0 = 0.f, cp1 = 0.f;

    for (int kc = 0; kc < NCH; kc++) {
        const int b = kc & 1;
        const uint32_t mb = b ? mbar1 : mbar0;
        mbar_wait(mb, (kc >> 1) & 1);
        float* xb = buf + b * (CH * DV);

        // ---- LN stats ----
        #pragma unroll
        for (int r = 0; r < 2; r++) {
            const int p = 2 * w + r;
            const float4* row = (const float4*)xb + p * 256;
            float s = 0.f, ss = 0.f;
            #pragma unroll
            for (int c = 0; c < 8; c++) {
                float4 v = row[c * 32 + lane];
                s  += (v.x + v.y) + (v.z + v.w);
                ss += v.x * v.x + v.y * v.y + v.z * v.z + v.w * v.w;
            }
            #pragma unroll
            for (int o = 16; o; o >>= 1) {
                s  += __shfl_xor_sync(0xffffffffu, s,  o);
                ss += __shfl_xor_sync(0xffffffffu, ss, o);
            }
            if (lane == 0) {
                float m = s * (1.f / 1024.f);
                mu[kc * CH + p] = m;
                rsig[kc * CH + p] = rsqrtf(ss * (1.f / 1024.f) - m * m + 1e-5f);
            }
        }
        __syncthreads();

        // ---- scores ----
        {
            const ulonglong2* x2 = (const ulonglong2*)xb;
            for (int p = 0; p < CH; p++) {
                const ulonglong2* row = x2 + p * 256;
                u64 a0 = 0ull, a1 = 0ull;
                #pragma unroll
                for (int c = 0; c < 8; c++) {
                    ulonglong2 xv = row[c * 32 + lane];
                    a0 = fma2(xv.x, wA[2*c],   a0);
                    a0 = fma2(xv.y, wA[2*c+1], a0);
                    a1 = fma2(xv.x, wB[2*c],   a1);
                    a1 = fma2(xv.y, wB[2*c+1], a1);
                }
                float l0, h0, l1, h1;
                unpack2(a0, l0, h0); unpack2(a1, l1, h1);
                float d0 = l0 + h0, d1 = l1 + h1;
                #pragma unroll
                for (int o = 16; o; o >>= 1) {
                    d0 += __shfl_xor_sync(0xffffffffu, d0, o);
                    d1 += __shfl_xor_sync(0xffffffffu, d1, o);
                }
                if (lane == 0) {
                    float r = rsig[kc * CH + p], q = r * mu[kc * CH + p];
                    sc[nh0 * 256 + kc * CH + p] = fmaf(r, d0, fmaf(-q, gw0, sb0));
                    sc[nh1 * 256 + kc * CH + p] = fmaf(r, d1, fmaf(-q, gw1, sb1));
                }
            }
        }
        __syncthreads();

        // ---- online softmax update ----
        {
            const int pl = lane & 15;
            float v0 = sc[nh0 * 256 + kc * CH + pl];
            float v1 = sc[nh1 * 256 + kc * CH + pl];
            if (lane >= 16) { v0 = -1e30f; v1 = -1e30f; }
            float c0 = v0, c1 = v1;
            #pragma unroll
            for (int o = 8; o; o >>= 1) {
                c0 = fmaxf(c0, __shfl_xor_sync(0xffffffffu, c0, o));
                c1 = fmaxf(c1, __shfl_xor_sync(0xffffffffu, c1, o));
            }
            float mn0 = fmaxf(m0, c0), mn1 = fmaxf(m1, c1);
            float f0 = __expf(m0 - mn0), f1 = __expf(m1 - mn1);
            float e0 = (lane < 16) ? __expf(v0 - mn0) : 0.f;
            float e1 = (lane < 16) ? __expf(v1 - mn1) : 0.f;
            float rs = rsig[kc * CH + pl], mv = mu[kc * CH + pl];
            float ar0 = e0 * rs, ar1 = e1 * rs;
            float su0 = e0, su1 = e1, cq0 = ar0 * mv, cq1 = ar1 * mv;
            #pragma unroll
            for (int o = 8; o; o >>= 1) {
                su0 += __shfl_xor_sync(0xffffffffu, su0, o);
                su1 += __shfl_xor_sync(0xffffffffu, su1, o);
                cq0 += __shfl_xor_sync(0xffffffffu, cq0, o);
                cq1 += __shfl_xor_sync(0xffffffffu, cq1, o);
            }
            s0 = s0 * f0 + su0;   s1 = s1 * f1 + su1;
            cp0 = cp0 * f0 + cq0; cp1 = cp1 * f1 + cq1;
            m0 = mn0; m1 = mn1;
            if (lane < 16) ((float2*)ar2c)[pl * 8 + w] = make_float2(ar0, ar1);
            if (lane == 0) ((float2*)f2s)[w] = make_float2(f0, f1);
        }
        __syncthreads();

        // ---- yacc rescale + accumulate ----
        {
            #pragma unroll
            for (int pr = 0; pr < 8; pr++) {
                u64 f2 = ((const u64*)f2s)[pr];
                #pragma unroll
                for (int c = 0; c < 4; c++) yacc[pr][c] = mul2(yacc[pr][c], f2);
            }
            const float4* xs4 = (const float4*)xb;
            for (int lp = 0; lp < CH; lp++) {
                float4 xv = xs4[lp * 256 + t];
                u64 x0 = dup2(xv.x), x1 = dup2(xv.y), x2d = dup2(xv.z), x3 = dup2(xv.w);
                #pragma unroll
                for (int pr = 0; pr < 8; pr++) {
                    u64 a2 = ((const u64*)ar2c)[lp * 8 + pr];
                    yacc[pr][0] = fma2(a2, x0,  yacc[pr][0]);
                    yacc[pr][1] = fma2(a2, x1,  yacc[pr][1]);
                    yacc[pr][2] = fma2(a2, x2d, yacc[pr][2]);
                    yacc[pr][3] = fma2(a2, x3,  yacc[pr][3]);
                }
            }
        }
        __syncthreads();

        if (t == 0 && kc + 2 < NCH) {
            mbar_expect(mb, CHBYTES);
            bulk_g2s(bufu + b * CHBYTES, src + (size_t)(kc + 2) * CHBYTES, CHBYTES, mb);
        }
    }

    if (lane == 0) {
        float is0 = 1.f / s0, is1 = 1.f / s1;
        invsr[nh0] = is0;        invsr[nh1] = is1;
        ccrow[nh0] = cp0 * is0;  ccrow[nh1] = cp1 * is1;
        mrow[nh0] = m0;          mrow[nh1] = m1;
    }
    __syncthreads();

    {
        float4 g4 = ((const float4*)gamma)[t];
        float4 b4 = ((const float4*)beta)[t];
        u64 gd[4] = { dup2(g4.x), dup2(g4.y), dup2(g4.z), dup2(g4.w) };
        u64 bd[4] = { dup2(b4.x), dup2(b4.y), dup2(b4.z), dup2(b4.w) };
        #pragma unroll
        for (int pr = 0; pr < 8; pr++) {
            u64 is2 = pack2(invsr[2*pr], invsr[2*pr+1]);
            u64 nc2 = pack2(-ccrow[2*pr], -ccrow[2*pr+1]);
            float o0[4], o1[4];
            #pragma unroll
            for (int c = 0; c < 4; c++) {
                u64 a = fma2(yacc[pr][c], is2, nc2);
                u64 o = fma2(a, gd[c], bd[c]);
                unpack2(o, o0[c], o1[c]);
            }
            float4 v0 = make_float4(o0[0], o0[1], o0[2], o0[3]);
            float4 v1 = make_float4(o1[0], o1[1], o1[2], o1[3]);
            ((float4*)(g_y + (size_t)((2*pr)     * BT + bt) * DV))[t] = v0;
            ((float4*)(g_y + (size_t)((2*pr + 1) * BT + bt) * DV))[t] = v1;
        }
    }

    if (w < 4) {
        const int n = w;
        float nrm = 0.f;
        #pragma unroll
        for (int i = 0; i < 8; i++) {
            int p = i * 32 + lane;
            float aa = 0.f;
            #pragma unroll
            for (int h = 0; h < 4; h++) {
                int r = 4 * n + h;
                aa += __expf(sc[r * 256 + p] - mrow[r]) * invsr[r];
            }
            aa *= 0.25f;
            av[n * 256 + p] = aa;
            nrm += aa * aa;
        }
        #pragma unroll
        for (int o = 16; o; o >>= 1) nrm += __shfl_xor_sync(0xffffffffu, nrm, o);
        if (lane == 0) avn[n] = 1.f / fmaxf(sqrtf(nrm), 1e-8f);
    }
    __syncthreads();
    if (w < 6) {
        const int pi[6] = {0, 0, 0, 1, 1, 2};
        const int pj[6] = {1, 2, 3, 2, 3, 3};
        int i = pi[w], j = pj[w];
        float dt = 0.f;
        #pragma unroll
        for (int c = 0; c < 8; c++) {
            int p = c * 32 + lane;
            dt += av[i * 256 + p] * av[j * 256 + p];
        }
        #pragma unroll
        for (int o = 16; o; o >>= 1) dt += __shfl_xor_sync(0xffffffffu, dt, o);
        if (lane == 0) g_sims[bt * 6 + w] = dt * avn[i] * avn[j];
    }
}

// =============================================================
// Kernel C v2: pooled[nh][bt][64] = y[nh][bt] @ Wv[n][:, h*64:+64] + bv
// grid (16 nh, 4 bt-tiles of 32), 256 threads.
// Register-prefetch pipelined over 16 K-chunks of 64; fma2 math.
// Thread (btq = t>>4, jq = t&15) computes 2 bt x 4 j.
// =============================================================
__global__ void __launch_bounds__(256, 1)
pooled_kernel(const float* __restrict__ Wv, const float* __restrict__ bv) {
    const int nh = blockIdx.x, btile = blockIdx.y;
    const int n = nh >> 2, h = nh & 3;
    __shared__ __align__(16) float wv_s[64 * 64];   // [d][j]
    __shared__ __align__(16) float ys[32 * 64];     // [b][d]
    const int t = threadIdx.x;
    const int btq = t >> 4, jq = t & 15;
    const int bt0 = btile * 32;
    const int b0 = btq * 2, b1 = btq * 2 + 1;

    // prefetch registers
    float4 wr[4], yr[2];
    // loader index decomposition (constant per thread)
    const int wd0 = t >> 4,          wq0 = t & 15;          // r=0..3 adds 16 to d
    const int yb0 = t >> 4,          yq0 = t & 15;          // r=0..1 adds 16 to b

    // ---- prefetch chunk 0 ----
    {
        const int kc = 0;
        #pragma unroll
        for (int r = 0; r < 4; r++)
            wr[r] = *(const float4*)(Wv + ((size_t)(n * DV + kc * 64 + wd0 + 16 * r)) * DB
                                     + h * 64 + wq0 * 4);
        #pragma unroll
        for (int r = 0; r < 2; r++)
            yr[r] = *(const float4*)(g_y + ((size_t)(nh * BT + bt0 + yb0 + 16 * r)) * DV
                                     + kc * 64 + yq0 * 4);
    }

    u64 acc00 = 0ull, acc01 = 0ull, acc10 = 0ull, acc11 = 0ull;

    for (int kc = 0; kc < 16; kc++) {
        // store staged regs to smem
        #pragma unroll
        for (int r = 0; r < 4; r++)
            *(float4*)(wv_s + (wd0 + 16 * r) * 64 + wq0 * 4) = wr[r];
        #pragma unroll
        for (int r = 0; r < 2; r++)
            *(float4*)(ys + (yb0 + 16 * r) * 64 + yq0 * 4) = yr[r];
        __syncthreads();

        // prefetch next chunk (LDG latency overlaps compute below)
        if (kc + 1 < 16) {
            const int kn = kc + 1;
            #pragma unroll
            for (int r = 0; r < 4; r++)
                wr[r] = *(const float4*)(Wv + ((size_t)(n * DV + kn * 64 + wd0 + 16 * r)) * DB
                                         + h * 64 + wq0 * 4);
            #pragma unroll
            for (int r = 0; r < 2; r++)
                yr[r] = *(const float4*)(g_y + ((size_t)(nh * BT + bt0 + yb0 + 16 * r)) * DV
                                         + kn * 64 + yq0 * 4);
        }

        // compute 64 k-steps from smem
        #pragma unroll 4
        for (int d4 = 0; d4 < 16; d4++) {
            float4 y0 = *(const float4*)(ys + b0 * 64 + d4 * 4);
            float4 y1 = *(const float4*)(ys + b1 * 64 + d4 * 4);
            float ya[4] = { y0.x, y0.y, y0.z, y0.w };
            float yb[4] = { y1.x, y1.y, y1.z, y1.w };
            #pragma unroll
            for (int dd = 0; dd < 4; dd++) {
                ulonglong2 w2 = *(const ulonglong2*)(wv_s + (d4 * 4 + dd) * 64 + jq * 4);
                u64 a = dup2(ya[dd]), b = dup2(yb[dd]);
                acc00 = fma2(a, w2.x, acc00);
                acc01 = fma2(a, w2.y, acc01);
                acc10 = fma2(b, w2.x, acc10);
                acc11 = fma2(b, w2.y, acc11);
            }
        }
        __syncthreads();
    }

    // bias + write
    float2 bv0 = ((const float2*)(bv + n * DB + h * 64))[jq * 2];
    float2 bv1 = ((const float2*)(bv + n * DB + h * 64))[jq * 2 + 1];
    u64 bvx = pack2(bv0.x, bv0.y), bvy = pack2(bv1.x, bv1.y);
    float r00a, r00b, r01a, r01b, r10a, r10b, r11a, r11b;
    unpack2(fma2(acc00, dup2(1.f), bvx), r00a, r00b);
    unpack2(fma2(acc01, dup2(1.f), bvy), r01a, r01b);
    unpack2(fma2(acc10, dup2(1.f), bvx), r10a, r10b);
    unpack2(fma2(acc11, dup2(1.f), bvy), r11a, r11b);
    float4 o0 = make_float4(r00a, r00b, r01a, r01b);
    float4 o1 = make_float4(r10a, r10b, r11a, r11b);
    *(float4*)(g_pooled + ((size_t)(n * BT + bt0 + b0)) * DB + h * 64 + jq * 4) = o0;
    *(float4*)(g_pooled + ((size_t)(n * BT + bt0 + b1)) * DB + h * 64 + jq * 4) = o1;
}

// =============================================================
// Kernel D v2: out = pooled @ Wo + bo, transposed write.
// grid (4 n, 8 bt-tiles of 16), 256 threads.
// Thread (btq = t>>4, mq = t&15) computes 1 bt x 16 m (m = g*64+mq*4).
// ps tile loaded once; Wo staged in 16 chunks of 16 k with reg prefetch.
// =============================================================
__global__ void __launch_bounds__(256, 1)
out_kernel(const float* __restrict__ Wo, const float* __restrict__ bo,
           float* __restrict__ out) {
    const int n = blockIdx.x, btile = blockIdx.y;
    __shared__ __align__(16) float ps[16 * 256];   // [bt][k]
    __shared__ __align__(16) float ws[16 * 256];   // [k][m]
    const int t = threadIdx.x;
    const int btq = t >> 4, mq = t & 15;

    // load full pooled tile (16 bt x 256 k)
    {
        const int b = t >> 6, q = t & 63;
        #pragma unroll
        for (int r = 0; r < 4; r++)
            *(float4*)(ps + (b + 4 * r) * 256 + q * 4) =
                *(const float4*)(g_pooled + ((size_t)(n * BT + btile * 16 + b + 4 * r)) * DB + q * 4);
    }

    // Wo chunk loader decomposition
    const int wk0 = t >> 6, wq0 = t & 63;
    float4 wr[4];
    #pragma unroll
    for (int r = 0; r < 4; r++)
        wr[r] = *(const float4*)(Wo + ((size_t)(n * DB + 0 * 16 + wk0 + 4 * r)) * DB + wq0 * 4);

    u64 acc[4][2];
    #pragma unroll
    for (int g = 0; g < 4; g++) { acc[g][0] = 0ull; acc[g][1] = 0ull; }

    for (int kc = 0; kc < 16; kc++) {
        #pragma unroll
        for (int r = 0; r < 4; r++)
            *(float4*)(ws + (wk0 + 4 * r) * 256 + wq0 * 4) = wr[r];
        __syncthreads();

        if (kc + 1 < 16) {
            #pragma unroll
            for (int r = 0; r < 4; r++)
                wr[r] = *(const float4*)(Wo + ((size_t)(n * DB + (kc + 1) * 16 + wk0 + 4 * r)) * DB
                                         + wq0 * 4);
        }

        #pragma unroll
        for (int k = 0; k < 16; k++) {
            u64 p2 = dup2(ps[btq * 256 + kc * 16 + k]);
            #pragma unroll
            for (int g = 0; g < 4; g++) {
                ulonglong2 w2 = *(const ulonglong2*)(ws + k * 256 + g * 64 + mq * 4);
                acc[g][0] = fma2(p2, w2.x, acc[g][0]);
                acc[g][1] = fma2(p2, w2.y, acc[g][1]);
            }
        }
        __syncthreads();
    }

    const int btg = btile * 16 + btq;
    #pragma unroll
    for (int g = 0; g < 4; g++) {
        int mbase = g * 64 + mq * 4;
        float a0, a1, a2, a3;
        unpack2(acc[g][0], a0, a1);
        unpack2(acc[g][1], a2, a3);
        float4 o;
        o.x = a0 + bo[n * DB + mbase + 0];
        o.y = a1 + bo[n * DB + mbase + 1];
        o.z = a2 + bo[n * DB + mbase + 2];
        o.w = a3 + bo[n * DB + mbase + 3];
        *((float4*)(out + ((size_t)btg * 4 + n) * DB + mbase)) = o;
    }
}

// =============================================================
// Kernel E: diversity loss finalize
// =============================================================
__global__ void loss_kernel(float* __restrict__ out) {
    __shared__ float part[6];
    const int t = threadIdx.x;
    if (t < 6) {
        float s = 0.f;
        for (int b = 0; b < BT; b++) s += g_sims[b * 6 + t];
        part[t] = s;
    }
    __syncthreads();
    if (t == 0) {
        float tot = part[0] + part[1] + part[2] + part[3] + part[4] + part[5];
        out[0] = 0.1f * (tot * (1.f / 128.f)) * (1.f / 6.f);
    }
}

// =============================================================
extern "C" void kernel_launch(void* const* d_in, const int* in_sizes, int n_in,
                              void* d_out, int out_size) {
    const float* frame = (const float*)d_in[0];
    const float* gam   = (const float*)d_in[1];
    const float* bet   = (const float*)d_in[2];
    const float* query = (const float*)d_in[3];
    const float* Wk    = (const float*)d_in[4];
    const float* bk    = (const float*)d_in[5];
    const float* Wv    = (const float*)d_in[6];
    const float* bv    = (const float*)d_in[7];
    const float* Wo    = (const float*)d_in[8];
    const float* bo    = (const float*)d_in[9];
    float* out = (float*)d_out;

    prep_kernel<<<16, 256>>>(Wk, query, bk, gam, bet);

    cudaFuncSetAttribute(main_kernel, cudaFuncAttributeMaxDynamicSharedMemorySize,
                         SMEM_MAIN_BYTES);
    main_kernel<<<128, 256, SMEM_MAIN_BYTES>>>(frame, gam, bet);

    pooled_kernel<<<dim3(16, 4), 256>>>(Wv, bv);
    out_kernel<<<dim3(4, 8), 256>>>(Wo, bo, out);

    if (out_size > BT * NBR * DB)
        loss_kernel<<<1, 32>>>(out + (size_t)BT * NBR * DB);
}

// round 4
// speedup vs baseline: 2.4875x; 1.1885x over previous
#include <cuda_runtime.h>
#include <math.h>
#include <stdint.h>

// Problem constants
#define BT   128          // B*T
#define NP   256          // patches
#define DV   1024         // D_VISION
#define NHD  16           // N_BRANCHES * N_HEADS
#define NBR  4
#define DB   256          // D_BRANCH
#define SCALE 0.125f      // HEAD_DIM^-0.5

#define CH    16          // patches per chunk (main kernel)
#define NCH   16          // chunks per bt
#define CHBYTES (CH * DV * 4)   // 65536

typedef unsigned long long u64;

// -------- device scratch (no allocation allowed) --------
__device__ __align__(16) float g_wqg[NHD * DV];
__device__ float g_gw [NHD];
__device__ float g_scb[NHD];
__device__ __align__(16) float g_y[(size_t)NHD * BT * DV];   // 8 MB
__device__ __align__(16) float g_pooled[NBR * BT * DB];
__device__ float g_sims[BT * 6];

// ---------------- f32x2 helpers ----------------
__device__ __forceinline__ u64 fma2(u64 a, u64 b, u64 c) {
    u64 d;
    asm("fma.rn.f32x2 %0, %1, %2, %3;" : "=l"(d) : "l"(a), "l"(b), "l"(c));
    return d;
}
__device__ __forceinline__ u64 mul2(u64 a, u64 b) {
    u64 d;
    asm("mul.rn.f32x2 %0, %1, %2;" : "=l"(d) : "l"(a), "l"(b));
    return d;
}
__device__ __forceinline__ u64 dup2(float v) {
    u64 r;
    asm("mov.b64 %0, {%1, %1};" : "=l"(r) : "f"(v));
    return r;
}
__device__ __forceinline__ u64 pack2(float lo, float hi) {
    u64 r;
    asm("mov.b64 %0, {%1, %2};" : "=l"(r) : "f"(lo), "f"(hi));
    return r;
}
__device__ __forceinline__ void unpack2(u64 v, float& lo, float& hi) {
    asm("mov.b64 {%0, %1}, %2;" : "=f"(lo), "=f"(hi) : "l"(v));
}

// ---------------- mbarrier / bulk-copy helpers ----------------
__device__ __forceinline__ uint32_t smem_u32(const void* p) {
    uint32_t a;
    asm("{ .reg .u64 t; cvta.to.shared.u64 t, %1; cvt.u32.u64 %0, t; }"
        : "=r"(a) : "l"(p));
    return a;
}
__device__ __forceinline__ void mbar_init(uint32_t mbar, uint32_t count) {
    asm volatile("mbarrier.init.shared.b64 [%0], %1;" :: "r"(mbar), "r"(count) : "memory");
}
__device__ __forceinline__ void mbar_expect(uint32_t mbar, uint32_t bytes) {
    asm volatile("mbarrier.arrive.expect_tx.shared.b64 _, [%0], %1;"
                 :: "r"(mbar), "r"(bytes) : "memory");
}
__device__ __forceinline__ void mbar_wait(uint32_t mbar, int phase) {
    asm volatile(
        "{\n\t.reg .pred P;\n\t"
        "WL_%=:\n\t"
        "mbarrier.try_wait.parity.acquire.cta.shared::cta.b64 P, [%0], %1, 0x989680;\n\t"
        "@P bra.uni WD_%=;\n\t"
        "bra.uni WL_%=;\n\t"
        "WD_%=:\n\t}"
        :: "r"(mbar), "r"(phase) : "memory");
}
__device__ __forceinline__ void bulk_g2s(uint32_t dst, const void* src,
                                         uint32_t bytes, uint32_t mbar) {
    asm volatile(
        "cp.async.bulk.shared::cluster.global.mbarrier::complete_tx::bytes [%0], [%1], %2, [%3];"
        :: "r"(dst), "l"(src), "r"(bytes), "r"(mbar) : "memory");
}

// =============================================================
// Kernel A: fold query into Wk (+ layernorm affine folding)
// =============================================================
__global__ void prep_kernel(const float* __restrict__ Wk,
                            const float* __restrict__ query,
                            const float* __restrict__ bk,
                            const float* __restrict__ gamma,
                            const float* __restrict__ beta) {
    const int nh = blockIdx.x;
    const int n = nh >> 2, h = nh & 3;
    __shared__ float q_s[64];
    __shared__ float r1[256], r2[256];
    const int t = threadIdx.x;
    if (t < 64) q_s[t] = query[(n * 4 + h) * 64 + t];
    __syncthreads();

    float gw_part = 0.f, bw_part = 0.f;
    const float4* qq = (const float4*)q_s;
    for (int d = t; d < DV; d += 256) {
        const float4* w4 = (const float4*)(Wk + ((size_t)(n * DV + d)) * DB + h * 64);
        float s = 0.f;
        #pragma unroll
        for (int j = 0; j < 16; j++) {
            float4 a = w4[j]; float4 b = qq[j];
            s += a.x * b.x + a.y * b.y + a.z * b.z + a.w * b.w;
        }
        g_wqg[nh * DV + d] = SCALE * gamma[d] * s;
        gw_part += gamma[d] * s;
        bw_part += beta[d] * s;
    }
    r1[t] = gw_part; r2[t] = bw_part;
    __syncthreads();
    for (int s = 128; s; s >>= 1) {
        if (t < s) { r1[t] += r1[t + s]; r2[t] += r2[t + s]; }
        __syncthreads();
    }
    if (t == 0) {
        float bq = 0.f;
        for (int j = 0; j < 64; j++) bq += bk[n * DB + h * 64 + j] * q_s[j];
        g_gw[nh]  = SCALE * r1[0];
        g_scb[nh] = SCALE * (r2[0] + bq);
    }
}

// =============================================================
// Kernel B v3: single-pass main kernel, 512 threads / 16 warps.
//  LN: warp w computes patch w stats.
//  scores: warp w -> rows 2*(w&7),+1 over patches (w>>3)*8..+8.
//  softmax (online): warp w -> row w.
//  yacc: thread owns 2 cols (2t, 2t+1), all 16 rows packed as 8 u64-pairs.
// =============================================================
#define SMEM_MAIN_FLOATS 38784
#define SMEM_MAIN_BYTES  (SMEM_MAIN_FLOATS * 4)

__global__ void __launch_bounds__(512, 1)
main_kernel(const float* __restrict__ frame,
            const float* __restrict__ gamma,
            const float* __restrict__ beta) {
    extern __shared__ float smf[];
    float* f2s   = smf + 4;     // 16 floats (u64-pairs per row-pair)
    float* mrow  = smf + 20;
    float* invsr = smf + 36;
    float* ccrow = smf + 52;
    float* avn   = smf + 68;
    float* mu    = smf + 128;
    float* rsig  = smf + 384;
    float* ar2c  = smf + 640;   // [patch 16][row 16] floats (u64 pair = row-pair)
    float* av    = smf + 896;
    float* sc    = smf + 1920;  // 16 x 256 raw scores
    float* buf   = smf + 6016;  // 2 x 16 x 1024

    const int t = threadIdx.x, w = t >> 5, lane = t & 31;
    const int bt = blockIdx.x;
    const uint32_t sbase = smem_u32(smf);
    const uint32_t mbar0 = sbase, mbar1 = sbase + 8;
    const uint32_t bufu = smem_u32(buf);

    const int rowA = 2 * (w & 7), rowB = rowA + 1;   // scores rows
    const int pbase = (w >> 3) * 8;                  // scores patch half

    // persistent folded-query weights (f32x2) for 2 rows
    u64 wA[16], wB[16];
    {
        const ulonglong2* wa = (const ulonglong2*)(g_wqg + rowA * DV);
        const ulonglong2* wb = (const ulonglong2*)(g_wqg + rowB * DV);
        #pragma unroll
        for (int c = 0; c < 8; c++) {
            ulonglong2 va = wa[c * 32 + lane]; wA[2*c] = va.x; wA[2*c+1] = va.y;
            ulonglong2 vb = wb[c * 32 + lane]; wB[2*c] = vb.x; wB[2*c+1] = vb.y;
        }
    }
    const float gwA = g_gw[rowA], gwB = g_gw[rowB];
    const float sbA = g_scb[rowA], sbB = g_scb[rowB];

    if (t == 0) { mbar_init(mbar0, 1); mbar_init(mbar1, 1); }
    __syncthreads();

    const char* src = (const char*)(frame + (size_t)bt * NP * DV);
    if (t == 0) {
        mbar_expect(mbar0, CHBYTES);
        bulk_g2s(bufu, src, CHBYTES, mbar0);
        mbar_expect(mbar1, CHBYTES);
        bulk_g2s(bufu + CHBYTES, src + CHBYTES, CHBYTES, mbar1);
    }

    // yacc: thread owns cols (2t, 2t+1); rows packed pairwise into u64 lanes
    u64 yacc[8][2];
    #pragma unroll
    for (int pr = 0; pr < 8; pr++) { yacc[pr][0] = 0ull; yacc[pr][1] = 0ull; }

    // online softmax state for row w (valid on lanes < 16; lane 0 canonical)
    float mO = -1e30f, sO = 0.f, cpO = 0.f;

    for (int kc = 0; kc < NCH; kc++) {
        const int b = kc & 1;
        const uint32_t mb = b ? mbar1 : mbar0;
        mbar_wait(mb, (kc >> 1) & 1);
        float* xb = buf + b * (CH * DV);

        // ---- LN stats: warp w handles patch w ----
        {
            const float4* row = (const float4*)xb + w * 256;
            float s = 0.f, ss = 0.f;
            #pragma unroll
            for (int c = 0; c < 8; c++) {
                float4 v = row[c * 32 + lane];
                s  += (v.x + v.y) + (v.z + v.w);
                ss += v.x * v.x + v.y * v.y + v.z * v.z + v.w * v.w;
            }
            #pragma unroll
            for (int o = 16; o; o >>= 1) {
                s  += __shfl_xor_sync(0xffffffffu, s,  o);
                ss += __shfl_xor_sync(0xffffffffu, ss, o);
            }
            if (lane == 0) {
                float m = s * (1.f / 1024.f);
                mu[kc * CH + w] = m;
                rsig[kc * CH + w] = rsqrtf(ss * (1.f / 1024.f) - m * m + 1e-5f);
            }
        }
        __syncthreads();

        // ---- scores: 2 rows x 8 patches per warp, patch-pair unrolled ----
        {
            const ulonglong2* x2 = (const ulonglong2*)xb;
            #pragma unroll
            for (int pp = 0; pp < 4; pp++) {
                const int p0 = pbase + 2 * pp, p1 = p0 + 1;
                const ulonglong2* r0 = x2 + p0 * 256;
                const ulonglong2* r1 = x2 + p1 * 256;
                u64 a00 = 0ull, a01 = 0ull, a10 = 0ull, a11 = 0ull;
                #pragma unroll
                for (int c = 0; c < 8; c++) {
                    ulonglong2 x0 = r0[c * 32 + lane];
                    ulonglong2 x1 = r1[c * 32 + lane];
                    a00 = fma2(x0.x, wA[2*c],   a00);
                    a00 = fma2(x0.y, wA[2*c+1], a00);
                    a01 = fma2(x0.x, wB[2*c],   a01);
                    a01 = fma2(x0.y, wB[2*c+1], a01);
                    a10 = fma2(x1.x, wA[2*c],   a10);
                    a10 = fma2(x1.y, wA[2*c+1], a10);
                    a11 = fma2(x1.x, wB[2*c],   a11);
                    a11 = fma2(x1.y, wB[2*c+1], a11);
                }
                float l, h2;
                unpack2(a00, l, h2); float d00 = l + h2;
                unpack2(a01, l, h2); float d01 = l + h2;
                unpack2(a10, l, h2); float d10 = l + h2;
                unpack2(a11, l, h2); float d11 = l + h2;
                #pragma unroll
                for (int o = 16; o; o >>= 1) {
                    d00 += __shfl_xor_sync(0xffffffffu, d00, o);
                    d01 += __shfl_xor_sync(0xffffffffu, d01, o);
                    d10 += __shfl_xor_sync(0xffffffffu, d10, o);
                    d11 += __shfl_xor_sync(0xffffffffu, d11, o);
                }
                if (lane == 0) {
                    int g0 = kc * CH + p0, g1 = kc * CH + p1;
                    float r = rsig[g0], q = r * mu[g0];
                    sc[rowA * 256 + g0] = fmaf(r, d00, fmaf(-q, gwA, sbA));
                    sc[rowB * 256 + g0] = fmaf(r, d01, fmaf(-q, gwB, sbB));
                    r = rsig[g1]; q = r * mu[g1];
                    sc[rowA * 256 + g1] = fmaf(r, d10, fmaf(-q, gwA, sbA));
                    sc[rowB * 256 + g1] = fmaf(r, d11, fmaf(-q, gwB, sbB));
                }
            }
        }
        __syncthreads();

        // ---- online softmax update: warp w -> row w ----
        {
            const int pl = lane & 15;
            float v = (lane < 16) ? sc[w * 256 + kc * CH + pl] : -1e30f;
            float c = v;
            #pragma unroll
            for (int o = 8; o; o >>= 1)
                c = fmaxf(c, __shfl_xor_sync(0xffffffffu, c, o));
            float mn = fmaxf(mO, c);
            float f = __expf(mO - mn);
            float e = (lane < 16) ? __expf(v - mn) : 0.f;
            float rs = rsig[kc * CH + pl], mv = mu[kc * CH + pl];
            float ar = e * rs;
            float su = e, cq = ar * mv;
            #pragma unroll
            for (int o = 8; o; o >>= 1) {
                su += __shfl_xor_sync(0xffffffffu, su, o);
                cq += __shfl_xor_sync(0xffffffffu, cq, o);
            }
            sO = sO * f + su;
            cpO = cpO * f + cq;
            mO = mn;
            if (lane < 16) ar2c[pl * 16 + w] = ar;
            if (lane == 0) f2s[w] = f;
        }
        __syncthreads();

        // ---- yacc rescale + accumulate ----
        {
            #pragma unroll
            for (int pr = 0; pr < 8; pr++) {
                u64 f2 = ((const u64*)f2s)[pr];
                yacc[pr][0] = mul2(yacc[pr][0], f2);
                yacc[pr][1] = mul2(yacc[pr][1], f2);
            }
            const float2* xs2 = (const float2*)xb;
            #pragma unroll 2
            for (int lp = 0; lp < CH; lp++) {
                float2 xv = xs2[lp * 512 + t];
                u64 x0 = dup2(xv.x), x1 = dup2(xv.y);
                const ulonglong2* arp = (const ulonglong2*)(ar2c + lp * 16);
                #pragma unroll
                for (int pq = 0; pq < 4; pq++) {
                    ulonglong2 a2 = arp[pq];
                    yacc[2*pq][0]   = fma2(a2.x, x0, yacc[2*pq][0]);
                    yacc[2*pq][1]   = fma2(a2.x, x1, yacc[2*pq][1]);
                    yacc[2*pq+1][0] = fma2(a2.y, x0, yacc[2*pq+1][0]);
                    yacc[2*pq+1][1] = fma2(a2.y, x1, yacc[2*pq+1][1]);
                }
            }
        }
        __syncthreads();   // buffer b free

        if (t == 0 && kc + 2 < NCH) {
            mbar_expect(mb, CHBYTES);
            bulk_g2s(bufu + b * CHBYTES, src + (size_t)(kc + 2) * CHBYTES, CHBYTES, mb);
        }
    }

    // ---- finalize per-row softmax state ----
    if (lane == 0) {
        float is = 1.f / sO;
        invsr[w] = is;
        ccrow[w] = cpO * is;
        mrow[w]  = mO;
    }
    __syncthreads();

    // ---- epilogue: y = gamma*(yacc/s - cc) + beta -> g_y ----
    {
        float2 g2 = ((const float2*)gamma)[t];
        float2 b2 = ((const float2*)beta)[t];
        u64 gd0 = dup2(g2.x), gd1 = dup2(g2.y);
        u64 bd0 = dup2(b2.x), bd1 = dup2(b2.y);
        #pragma unroll
        for (int pr = 0; pr < 8; pr++) {
            u64 is2 = pack2(invsr[2*pr], invsr[2*pr+1]);
            u64 nc2 = pack2(-ccrow[2*pr], -ccrow[2*pr+1]);
            u64 o0 = fma2(fma2(yacc[pr][0], is2, nc2), gd0, bd0);
            u64 o1 = fma2(fma2(yacc[pr][1], is2, nc2), gd1, bd1);
            float a0, b0v, a1, b1v;
            unpack2(o0, a0, b0v);   // (rowA col0, rowB col0)
            unpack2(o1, a1, b1v);   // (rowA col1, rowB col1)
            ((float2*)(g_y + (size_t)((2*pr)     * BT + bt) * DV))[t] = make_float2(a0, a1);
            ((float2*)(g_y + (size_t)((2*pr + 1) * BT + bt) * DV))[t] = make_float2(b0v, b1v);
        }
    }

    // ---- diversity partials (recompute attn from raw scores) ----
    if (w < 4) {
        const int n = w;
        float nrm = 0.f;
        #pragma unroll
        for (int i = 0; i < 8; i++) {
            int p = i * 32 + lane;
            float aa = 0.f;
            #pragma unroll
            for (int h = 0; h < 4; h++) {
                int r = 4 * n + h;
                aa += __expf(sc[r * 256 + p] - mrow[r]) * invsr[r];
            }
            aa *= 0.25f;
            av[n * 256 + p] = aa;
            nrm += aa * aa;
        }
        #pragma unroll
        for (int o = 16; o; o >>= 1) nrm += __shfl_xor_sync(0xffffffffu, nrm, o);
        if (lane == 0) avn[n] = 1.f / fmaxf(sqrtf(nrm), 1e-8f);
    }
    __syncthreads();
    if (w < 6) {
        const int pi[6] = {0, 0, 0, 1, 1, 2};
        const int pj[6] = {1, 2, 3, 2, 3, 3};
        int i = pi[w], j = pj[w];
        float dt = 0.f;
        #pragma unroll
        for (int c = 0; c < 8; c++) {
            int p = c * 32 + lane;
            dt += av[i * 256 + p] * av[j * 256 + p];
        }
        #pragma unroll
        for (int o = 16; o; o >>= 1) dt += __shfl_xor_sync(0xffffffffu, dt, o);
        if (lane == 0) g_sims[bt * 6 + w] = dt * avn[i] * avn[j];
    }
}

// =============================================================
// Kernel C v3: pooled = y @ Wv-slice + bv.
// grid (16 nh, 8 tiles of 16 bt), 256 threads; bt in LOW lane bits
// so Wv smem reads broadcast within warps. Reg-prefetch pipelined.
// =============================================================
__global__ void __launch_bounds__(256, 1)
pooled_kernel(const float* __restrict__ Wv, const float* __restrict__ bv) {
    const int nh = blockIdx.x, btile = blockIdx.y;
    const int n = nh >> 2, h = nh & 3;
    __shared__ __align__(16) float wv_s[64 * 64];   // [d][j]
    __shared__ __align__(16) float ys[16 * 68];     // [bt][k] padded
    const int t = threadIdx.x;
    const int btq = t & 15, jq = t >> 4;            // jq 0..15 -> j = jq*4
    const int bt0 = btile * 16;

    // loader decomposition
    const int wd0 = t >> 4, wq0 = t & 15;   // wv: d = wd0+16r, col4 = wq0
    const int yb0 = t & 15, yk0 = t >> 4;   // ys: bt = yb0, k4 = yk0

    float4 wr[4], yr;
    {
        #pragma unroll
        for (int r = 0; r < 4; r++)
            wr[r] = *(const float4*)(Wv + ((size_t)(n * DV + wd0 + 16 * r)) * DB
                                     + h * 64 + wq0 * 4);
        yr = *(const float4*)(g_y + ((size_t)(nh * BT + bt0 + yb0)) * DV + yk0 * 4);
    }

    u64 acc0 = 0ull, acc1 = 0ull;

    for (int kc = 0; kc < 16; kc++) {
        #pragma unroll
        for (int r = 0; r < 4; r++)
            *(float4*)(wv_s + (wd0 + 16 * r) * 64 + wq0 * 4) = wr[r];
        *(float4*)(ys + yb0 * 68 + yk0 * 4) = yr;
        __syncthreads();

        if (kc + 1 < 16) {
            const int kn = kc + 1;
            #pragma unroll
            for (int r = 0; r < 4; r++)
                wr[r] = *(const float4*)(Wv + ((size_t)(n * DV + kn * 64 + wd0 + 16 * r)) * DB
                                         + h * 64 + wq0 * 4);
            yr = *(const float4*)(g_y + ((size_t)(nh * BT + bt0 + yb0)) * DV
                                  + kn * 64 + yk0 * 4);
        }

        #pragma unroll 4
        for (int k4 = 0; k4 < 16; k4++) {
            float4 yv = *(const float4*)(ys + btq * 68 + k4 * 4);
            float ya[4] = { yv.x, yv.y, yv.z, yv.w };
            #pragma unroll
            for (int dd = 0; dd < 4; dd++) {
                ulonglong2 w2 = *(const ulonglong2*)(wv_s + (k4 * 4 + dd) * 64 + jq * 4);
                u64 a = dup2(ya[dd]);
                acc0 = fma2(a, w2.x, acc0);
                acc1 = fma2(a, w2.y, acc1);
            }
        }
        __syncthreads();
    }

    float a0, a1, a2, a3;
    unpack2(acc0, a0, a1);
    unpack2(acc1, a2, a3);
    const float* bvp = bv + n * DB + h * 64 + jq * 4;
    float4 o = make_float4(a0 + bvp[0], a1 + bvp[1], a2 + bvp[2], a3 + bvp[3]);
    *(float4*)(g_pooled + ((size_t)(n * BT + bt0 + btq)) * DB + h * 64 + jq * 4) = o;
}

// =============================================================
// Kernel D v3: out = pooled @ Wo + bo, transposed write.
// grid (4 n, 16 tiles of 8 bt), 256 threads; btq = t&7 (low bits)
// so Wo smem reads are shared across lanes. Reg-prefetch pipelined.
// =============================================================
__global__ void __launch_bounds__(256, 1)
out_kernel(const float* __restrict__ Wo, const float* __restrict__ bo,
           float* __restrict__ out) {
    const int n = blockIdx.x, btile = blockIdx.y;
    __shared__ __align__(16) float ps[8 * 260];    // [bt][k] padded (260 keeps 16B align)
    __shared__ __align__(16) float ws[16 * 256];   // [k][m]
    const int t = threadIdx.x;
    const int btq = t & 7, mq = t >> 3;            // mq 0..31 -> m = mq*8
    const int bt0 = btile * 8;

    // load full pooled tile 8 bt x 256 k
    {
        const int b = t >> 5, q = t & 31;
        #pragma unroll
        for (int r = 0; r < 2; r++)
            *(float4*)(ps + b * 260 + q * 4 + 128 * r) =
                *(const float4*)(g_pooled + ((size_t)(n * BT + bt0 + b)) * DB + q * 4 + 128 * r);
    }

    // Wo chunk loader: k = wk0 + 4r, m4 = wq0
    const int wk0 = t >> 6, wq0 = t & 63;
    float4 wr[4];
    #pragma unroll
    for (int r = 0; r < 4; r++)
        wr[r] = *(const float4*)(Wo + ((size_t)(n * DB + wk0 + 4 * r)) * DB + wq0 * 4);

    u64 acc[4];
    #pragma unroll
    for (int g = 0; g < 4; g++) acc[g] = 0ull;

    for (int kc = 0; kc < 16; kc++) {
        #pragma unroll
        for (int r = 0; r < 4; r++)
            *(float4*)(ws + (wk0 + 4 * r) * 256 + wq0 * 4) = wr[r];
        __syncthreads();

        if (kc + 1 < 16) {
            #pragma unroll
            for (int r = 0; r < 4; r++)
                wr[r] = *(const float4*)(Wo + ((size_t)(n * DB + (kc + 1) * 16 + wk0 + 4 * r)) * DB
                                         + wq0 * 4);
        }

        #pragma unroll
        for (int k = 0; k < 16; k++) {
            u64 p2 = dup2(ps[btq * 260 + kc * 16 + k]);
            ulonglong2 wa = *(const ulonglong2*)(ws + k * 256 + mq * 8);
            ulonglong2 wb = *(const ulonglong2*)(ws + k * 256 + mq * 8 + 4);
            acc[0] = fma2(p2, wa.x, acc[0]);
            acc[1] = fma2(p2, wa.y, acc[1]);
            acc[2] = fma2(p2, wb.x, acc[2]);
            acc[3] = fma2(p2, wb.y, acc[3]);
        }
        __syncthreads();
    }

    const int btg = bt0 + btq;
    float v[8];
    unpack2(acc[0], v[0], v[1]);
    unpack2(acc[1], v[2], v[3]);
    unpack2(acc[2], v[4], v[5]);
    unpack2(acc[3], v[6], v[7]);
    const float* bop = bo + n * DB + mq * 8;
    float* dst = out + ((size_t)btg * 4 + n) * DB + mq * 8;
    float4 o0 = make_float4(v[0] + bop[0], v[1] + bop[1], v[2] + bop[2], v[3] + bop[3]);
    float4 o1 = make_float4(v[4] + bop[4], v[5] + bop[5], v[6] + bop[6], v[7] + bop[7]);
    ((float4*)dst)[0] = o0;
    ((float4*)dst)[1] = o1;
}

// =============================================================
// Kernel E: diversity loss finalize
// =============================================================
__global__ void loss_kernel(float* __restrict__ out) {
    __shared__ float part[6];
    const int t = threadIdx.x;
    if (t < 6) {
        float s = 0.f;
        for (int b = 0; b < BT; b++) s += g_sims[b * 6 + t];
        part[t] = s;
    }
    __syncthreads();
    if (t == 0) {
        float tot = part[0] + part[1] + part[2] + part[3] + part[4] + part[5];
        out[0] = 0.1f * (tot * (1.f / 128.f)) * (1.f / 6.f);
    }
}

// =============================================================
extern "C" void kernel_launch(void* const* d_in, const int* in_sizes, int n_in,
                              void* d_out, int out_size) {
    const float* frame = (const float*)d_in[0];
    const float* gam   = (const float*)d_in[1];
    const float* bet   = (const float*)d_in[2];
    const float* query = (const float*)d_in[3];
    const float* Wk    = (const float*)d_in[4];
    const float* bk    = (const float*)d_in[5];
    const float* Wv    = (const float*)d_in[6];
    const float* bv    = (const float*)d_in[7];
    const float* Wo    = (const float*)d_in[8];
    const float* bo    = (const float*)d_in[9];
    float* out = (float*)d_out;

    prep_kernel<<<16, 256>>>(Wk, query, bk, gam, bet);

    cudaFuncSetAttribute(main_kernel, cudaFuncAttributeMaxDynamicSharedMemorySize,
                         SMEM_MAIN_BYTES);
    main_kernel<<<128, 512, SMEM_MAIN_BYTES>>>(frame, gam, bet);

    pooled_kernel<<<dim3(16, 8), 256>>>(Wv, bv);
    out_kernel<<<dim3(4, 16), 256>>>(Wo, bo, out);

    if (out_size > BT * NBR * DB)
        loss_kernel<<<1, 32>>>(out + (size_t)BT * NBR * DB);
}

// round 5
// speedup vs baseline: 2.9292x; 1.1775x over previous
#include <cuda_runtime.h>
#include <math.h>
#include <stdint.h>

// Problem constants
#define BT   128          // B*T
#define NP   256          // patches
#define DV   1024         // D_VISION
#define NHD  16           // N_BRANCHES * N_HEADS
#define NBR  4
#define DB   256          // D_BRANCH
#define SCALE 0.125f      // HEAD_DIM^-0.5

#define CH    16          // patches per chunk (main kernel)
#define NCH   16          // chunks per bt
#define CHBYTES (CH * DV * 4)   // 65536

typedef unsigned long long u64;

// -------- device scratch (no allocation allowed) --------
__device__ __align__(16) float g_wqg[NHD * DV];
__device__ float g_gw [NHD];
__device__ float g_scb[NHD];
__device__ __align__(16) float g_y[(size_t)NHD * BT * DV];   // 8 MB
__device__ __align__(16) float g_pooled[NBR * BT * DB];
__device__ float g_sims[BT * 6];

// ---------------- f32x2 helpers ----------------
__device__ __forceinline__ u64 fma2(u64 a, u64 b, u64 c) {
    u64 d;
    asm("fma.rn.f32x2 %0, %1, %2, %3;" : "=l"(d) : "l"(a), "l"(b), "l"(c));
    return d;
}
__device__ __forceinline__ u64 mul2(u64 a, u64 b) {
    u64 d;
    asm("mul.rn.f32x2 %0, %1, %2;" : "=l"(d) : "l"(a), "l"(b));
    return d;
}
__device__ __forceinline__ u64 add2(u64 a, u64 b) {
    u64 d;
    asm("add.rn.f32x2 %0, %1, %2;" : "=l"(d) : "l"(a), "l"(b));
    return d;
}
__device__ __forceinline__ u64 dup2(float v) {
    u64 r;
    asm("mov.b64 %0, {%1, %1};" : "=l"(r) : "f"(v));
    return r;
}
__device__ __forceinline__ u64 pack2(float lo, float hi) {
    u64 r;
    asm("mov.b64 %0, {%1, %2};" : "=l"(r) : "f"(lo), "f"(hi));
    return r;
}
__device__ __forceinline__ void unpack2(u64 v, float& lo, float& hi) {
    asm("mov.b64 {%0, %1}, %2;" : "=f"(lo), "=f"(hi) : "l"(v));
}

// ---------------- mbarrier / bulk-copy helpers ----------------
__device__ __forceinline__ uint32_t smem_u32(const void* p) {
    uint32_t a;
    asm("{ .reg .u64 t; cvta.to.shared.u64 t, %1; cvt.u32.u64 %0, t; }"
        : "=r"(a) : "l"(p));
    return a;
}
__device__ __forceinline__ void mbar_init(uint32_t mbar, uint32_t count) {
    asm volatile("mbarrier.init.shared.b64 [%0], %1;" :: "r"(mbar), "r"(count) : "memory");
}
__device__ __forceinline__ void mbar_expect(uint32_t mbar, uint32_t bytes) {
    asm volatile("mbarrier.arrive.expect_tx.shared.b64 _, [%0], %1;"
                 :: "r"(mbar), "r"(bytes) : "memory");
}
__device__ __forceinline__ void mbar_wait(uint32_t mbar, int phase) {
    asm volatile(
        "{\n\t.reg .pred P;\n\t"
        "WL_%=:\n\t"
        "mbarrier.try_wait.parity.acquire.cta.shared::cta.b64 P, [%0], %1, 0x989680;\n\t"
        "@P bra.uni WD_%=;\n\t"
        "bra.uni WL_%=;\n\t"
        "WD_%=:\n\t}"
        :: "r"(mbar), "r"(phase) : "memory");
}
__device__ __forceinline__ void bulk_g2s(uint32_t dst, const void* src,
                                         uint32_t bytes, uint32_t mbar) {
    asm volatile(
        "cp.async.bulk.shared::cluster.global.mbarrier::complete_tx::bytes [%0], [%1], %2, [%3];"
        :: "r"(dst), "l"(src), "r"(bytes), "r"(mbar) : "memory");
}

// =============================================================
// Kernel A: fold query into Wk (+ layernorm affine folding)
// =============================================================
__global__ void prep_kernel(const float* __restrict__ Wk,
                            const float* __restrict__ query,
                            const float* __restrict__ bk,
                            const float* __restrict__ gamma,
                            const float* __restrict__ beta) {
    const int nh = blockIdx.x;
    const int n = nh >> 2, h = nh & 3;
    __shared__ float q_s[64];
    __shared__ float r1[256], r2[256];
    const int t = threadIdx.x;
    if (t < 64) q_s[t] = query[(n * 4 + h) * 64 + t];
    __syncthreads();

    float gw_part = 0.f, bw_part = 0.f;
    const float4* qq = (const float4*)q_s;
    for (int d = t; d < DV; d += 256) {
        const float4* w4 = (const float4*)(Wk + ((size_t)(n * DV + d)) * DB + h * 64);
        float s = 0.f;
        #pragma unroll
        for (int j = 0; j < 16; j++) {
            float4 a = w4[j]; float4 b = qq[j];
            s += a.x * b.x + a.y * b.y + a.z * b.z + a.w * b.w;
        }
        g_wqg[nh * DV + d] = SCALE * gamma[d] * s;
        gw_part += gamma[d] * s;
        bw_part += beta[d] * s;
    }
    r1[t] = gw_part; r2[t] = bw_part;
    __syncthreads();
    for (int s = 128; s; s >>= 1) {
        if (t < s) { r1[t] += r1[t + s]; r2[t] += r2[t + s]; }
        __syncthreads();
    }
    if (t == 0) {
        float bq = 0.f;
        for (int j = 0; j < 64; j++) bq += bk[n * DB + h * 64 + j] * q_s[j];
        g_gw[nh]  = SCALE * r1[0];
        g_scb[nh] = SCALE * (r2[0] + bq);
    }
}

// =============================================================
// Kernel B v4: single-pass main kernel, 256 threads / 8 warps.
//  LN: warp w -> patches 2w, 2w+1.
//  scores: warp w -> 4 rows (rg=w&3), 8 patches (pg=w>>2); packed
//          select+xor shuffle tree (8 dots in 9 shuffles).
//  softmax: warp w -> rows 2w (lanes 0-15) and 2w+1 (lanes 16-31).
//  yacc: thread owns 4 cols; rows packed pairwise into u64 lanes.
// =============================================================
#define SMEM_MAIN_FLOATS 38784
#define SMEM_MAIN_BYTES  (SMEM_MAIN_FLOATS * 4)

__global__ void __launch_bounds__(256, 1)
main_kernel(const float* __restrict__ frame,
            const float* __restrict__ gamma,
            const float* __restrict__ beta) {
    extern __shared__ float smf[];
    float* f2s   = smf + 4;     // 16 (u64-pairs per row-pair)
    float* mrow  = smf + 20;
    float* invsr = smf + 36;
    float* ccrow = smf + 52;
    float* avn   = smf + 68;    // 4
    float* s_gw  = smf + 72;    // 16
    float* s_scb = smf + 88;    // 16
    float* mu    = smf + 128;
    float* rsig  = smf + 384;
    float* ar2c  = smf + 640;   // [patch 16][row 16]
    float* av    = smf + 896;
    float* sc    = smf + 1920;  // 16 x 256 raw scores
    float* buf   = smf + 6016;  // 2 x 16 x 1024

    const int t = threadIdx.x, w = t >> 5, lane = t & 31;
    const int bt = blockIdx.x;
    const uint32_t sbase = smem_u32(smf);
    const uint32_t mbar0 = sbase, mbar1 = sbase + 8;
    const uint32_t bufu = smem_u32(buf);

    const int rg = w & 3, pg = w >> 2;
    const int rbase = rg * 4;

    // persistent folded-query weights for 4 rows (128 regs)
    u64 wR[4][16];
    #pragma unroll
    for (int rr = 0; rr < 4; rr++) {
        const ulonglong2* wp = (const ulonglong2*)(g_wqg + (rbase + rr) * DV);
        #pragma unroll
        for (int c = 0; c < 8; c++) {
            ulonglong2 v = wp[c * 32 + lane];
            wR[rr][2*c] = v.x; wR[rr][2*c+1] = v.y;
        }
    }

    if (t < 16) { s_gw[t] = g_gw[t]; s_scb[t] = g_scb[t]; }
    if (t == 0) { mbar_init(mbar0, 1); mbar_init(mbar1, 1); }
    __syncthreads();

    const char* src = (const char*)(frame + (size_t)bt * NP * DV);
    if (t == 0) {
        mbar_expect(mbar0, CHBYTES);
        bulk_g2s(bufu, src, CHBYTES, mbar0);
        mbar_expect(mbar1, CHBYTES);
        bulk_g2s(bufu + CHBYTES, src + CHBYTES, CHBYTES, mbar1);
    }

    // yacc: thread owns cols 4t..4t+3; rows packed pairwise (8 pairs)
    u64 yacc[8][4];
    #pragma unroll
    for (int q = 0; q < 8; q++)
        #pragma unroll
        for (int c = 0; c < 4; c++) yacc[q][c] = 0ull;

    // softmax state: lanes 0-15 -> row 2w, lanes 16-31 -> row 2w+1
    const int half = lane >> 4, srow = 2 * w + half, pl = lane & 15;
    float mO = -1e30f, sO = 0.f, cpO = 0.f;

    for (int kc = 0; kc < NCH; kc++) {
        const int b = kc & 1;
        const uint32_t mb = b ? mbar1 : mbar0;
        mbar_wait(mb, (kc >> 1) & 1);
        float* xb = buf + b * (CH * DV);

        // ---- LN stats: warp w -> patches 2w, 2w+1 ----
        #pragma unroll
        for (int r = 0; r < 2; r++) {
            const int p = 2 * w + r;
            const float4* row = (const float4*)xb + p * 256;
            float s = 0.f, ss = 0.f;
            #pragma unroll
            for (int c = 0; c < 8; c++) {
                float4 v = row[c * 32 + lane];
                s  += (v.x + v.y) + (v.z + v.w);
                ss += v.x * v.x + v.y * v.y + v.z * v.z + v.w * v.w;
            }
            #pragma unroll
            for (int o = 16; o; o >>= 1) {
                s  += __shfl_xor_sync(0xffffffffu, s,  o);
                ss += __shfl_xor_sync(0xffffffffu, ss, o);
            }
            if (lane == 0) {
                float m = s * (1.f / 1024.f);
                mu[kc * CH + p] = m;
                rsig[kc * CH + p] = rsqrtf(ss * (1.f / 1024.f) - m * m + 1e-5f);
            }
        }
        __syncthreads();

        // ---- scores: 4 rows x 8 patches per warp ----
        {
            const ulonglong2* x2 = (const ulonglong2*)xb;
            const bool b16 = (lane & 16) != 0;
            const bool b8  = (lane & 8)  != 0;
            const bool b4  = (lane & 4)  != 0;
            #pragma unroll
            for (int pp = 0; pp < 4; pp++) {
                const int p0 = pg * 8 + 2 * pp, p1 = p0 + 1;
                const ulonglong2* r0 = x2 + p0 * 256;
                const ulonglong2* r1 = x2 + p1 * 256;
                u64 a[8];
                #pragma unroll
                for (int i = 0; i < 8; i++) a[i] = 0ull;
                #pragma unroll
                for (int c = 0; c < 8; c++) {
                    ulonglong2 x0 = r0[c * 32 + lane];
                    ulonglong2 x1 = r1[c * 32 + lane];
                    #pragma unroll
                    for (int rr = 0; rr < 4; rr++) {
                        a[2*rr]   = fma2(x0.x, wR[rr][2*c],   a[2*rr]);
                        a[2*rr]   = fma2(x0.y, wR[rr][2*c+1], a[2*rr]);
                        a[2*rr+1] = fma2(x1.x, wR[rr][2*c],   a[2*rr+1]);
                        a[2*rr+1] = fma2(x1.y, wR[rr][2*c+1], a[2*rr+1]);
                    }
                }
                float v[8];
                #pragma unroll
                for (int i = 0; i < 8; i++) {
                    float lo, hi;
                    unpack2(a[i], lo, hi);
                    v[i] = lo + hi;
                }
                // packed tree: 8 dots -> distributed lanes in 9 shuffles
                float u2[4];
                #pragma unroll
                for (int i = 0; i < 4; i++) {
                    float xx = b16 ? v[2*i] : v[2*i+1];
                    float tt = __shfl_xor_sync(0xffffffffu, xx, 16);
                    u2[i] = (b16 ? v[2*i+1] : v[2*i]) + tt;
                }
                float q2[2];
                #pragma unroll
                for (int i = 0; i < 2; i++) {
                    float xx = b8 ? u2[2*i] : u2[2*i+1];
                    float tt = __shfl_xor_sync(0xffffffffu, xx, 8);
                    q2[i] = (b8 ? u2[2*i+1] : u2[2*i]) + tt;
                }
                float z;
                {
                    float xx = b4 ? q2[0] : q2[1];
                    float tt = __shfl_xor_sync(0xffffffffu, xx, 4);
                    z = (b4 ? q2[1] : q2[0]) + tt;
                }
                z += __shfl_xor_sync(0xffffffffu, z, 2);
                z += __shfl_xor_sync(0xffffffffu, z, 1);
                if ((lane & 3) == 0) {
                    // lane holds v[idx]; idx = b16*1 + b8*2 + b4*4
                    int idx = ((lane >> 4) & 1) | ((lane >> 2) & 2) | (lane & 4);
                    int rr = idx >> 1, px = idx & 1;
                    int p = p0 + px;
                    int row = rbase + rr;
                    int gp = kc * CH + p;
                    float rv = rsig[gp], qv = rv * mu[gp];
                    sc[row * 256 + gp] = fmaf(rv, z, fmaf(-qv, s_gw[row], s_scb[row]));
                }
            }
        }
        __syncthreads();

        // ---- online softmax: 2 rows per warp in lane halves ----
        {
            float vv = sc[srow * 256 + kc * CH + pl];
            float c = vv;
            #pragma unroll
            for (int o = 8; o; o >>= 1)
                c = fmaxf(c, __shfl_xor_sync(0xffffffffu, c, o));
            float mn = fmaxf(mO, c);
            float f = __expf(mO - mn);
            float e = __expf(vv - mn);
            float rs = rsig[kc * CH + pl], mv = mu[kc * CH + pl];
            float ar = e * rs;
            float su = e, cq = ar * mv;
            #pragma unroll
            for (int o = 8; o; o >>= 1) {
                su += __shfl_xor_sync(0xffffffffu, su, o);
                cq += __shfl_xor_sync(0xffffffffu, cq, o);
            }
            sO = sO * f + su;
            cpO = cpO * f + cq;
            mO = mn;
            ar2c[pl * 16 + srow] = ar;
            if (pl == 0) f2s[srow] = f;
        }
        __syncthreads();

        // ---- yacc rescale + accumulate (4 cols/thread) ----
        {
            #pragma unroll
            for (int q = 0; q < 8; q++) {
                u64 f2 = ((const u64*)f2s)[q];
                #pragma unroll
                for (int c = 0; c < 4; c++) yacc[q][c] = mul2(yacc[q][c], f2);
            }
            const float4* xs4 = (const float4*)xb;
            #pragma unroll 2
            for (int lp = 0; lp < CH; lp++) {
                float4 xv = xs4[lp * 256 + t];
                u64 xd0 = dup2(xv.x), xd1 = dup2(xv.y);
                u64 xd2 = dup2(xv.z), xd3 = dup2(xv.w);
                const ulonglong2* arp = (const ulonglong2*)(ar2c + lp * 16);
                #pragma unroll
                for (int qq = 0; qq < 4; qq++) {
                    ulonglong2 a2 = arp[qq];
                    yacc[2*qq][0]   = fma2(a2.x, xd0, yacc[2*qq][0]);
                    yacc[2*qq][1]   = fma2(a2.x, xd1, yacc[2*qq][1]);
                    yacc[2*qq][2]   = fma2(a2.x, xd2, yacc[2*qq][2]);
                    yacc[2*qq][3]   = fma2(a2.x, xd3, yacc[2*qq][3]);
                    yacc[2*qq+1][0] = fma2(a2.y, xd0, yacc[2*qq+1][0]);
                    yacc[2*qq+1][1] = fma2(a2.y, xd1, yacc[2*qq+1][1]);
                    yacc[2*qq+1][2] = fma2(a2.y, xd2, yacc[2*qq+1][2]);
                    yacc[2*qq+1][3] = fma2(a2.y, xd3, yacc[2*qq+1][3]);
                }
            }
        }
        __syncthreads();   // buffer b free

        if (t == 0 && kc + 2 < NCH) {
            mbar_expect(mb, CHBYTES);
            bulk_g2s(bufu + b * CHBYTES, src + (size_t)(kc + 2) * CHBYTES, CHBYTES, mb);
        }
    }

    // ---- finalize per-row softmax state (lanes 0 and 16 of each warp) ----
    if (pl == 0) {
        float is = 1.f / sO;
        invsr[srow] = is;
        ccrow[srow] = cpO * is;
        mrow[srow]  = mO;
    }
    __syncthreads();

    // ---- epilogue: y = gamma*(yacc/s - cc) + beta -> g_y (4 cols/thread) ----
    {
        float4 g4 = ((const float4*)gamma)[t];
        float4 b4 = ((const float4*)beta)[t];
        u64 gd[4] = { dup2(g4.x), dup2(g4.y), dup2(g4.z), dup2(g4.w) };
        u64 bd[4] = { dup2(b4.x), dup2(b4.y), dup2(b4.z), dup2(b4.w) };
        #pragma unroll
        for (int q = 0; q < 8; q++) {
            u64 is2 = pack2(invsr[2*q], invsr[2*q+1]);
            u64 nc2 = pack2(-ccrow[2*q], -ccrow[2*q+1]);
            float lo[4], hi[4];
            #pragma unroll
            for (int c = 0; c < 4; c++) {
                u64 o = fma2(fma2(yacc[q][c], is2, nc2), gd[c], bd[c]);
                unpack2(o, lo[c], hi[c]);
            }
            ((float4*)(g_y + (size_t)((2*q)     * BT + bt) * DV))[t] =
                make_float4(lo[0], lo[1], lo[2], lo[3]);
            ((float4*)(g_y + (size_t)((2*q + 1) * BT + bt) * DV))[t] =
                make_float4(hi[0], hi[1], hi[2], hi[3]);
        }
    }

    // ---- diversity partials (recompute attn from raw scores) ----
    if (w < 4) {
        const int n = w;
        float nrm = 0.f;
        #pragma unroll
        for (int i = 0; i < 8; i++) {
            int p = i * 32 + lane;
            float aa = 0.f;
            #pragma unroll
            for (int h = 0; h < 4; h++) {
                int r = 4 * n + h;
                aa += __expf(sc[r * 256 + p] - mrow[r]) * invsr[r];
            }
            aa *= 0.25f;
            av[n * 256 + p] = aa;
            nrm += aa * aa;
        }
        #pragma unroll
        for (int o = 16; o; o >>= 1) nrm += __shfl_xor_sync(0xffffffffu, nrm, o);
        if (lane == 0) avn[n] = 1.f / fmaxf(sqrtf(nrm), 1e-8f);
    }
    __syncthreads();
    if (w < 6) {
        const int pi[6] = {0, 0, 0, 1, 1, 2};
        const int pj[6] = {1, 2, 3, 2, 3, 3};
        int i = pi[w], j = pj[w];
        float dt = 0.f;
        #pragma unroll
        for (int c = 0; c < 8; c++) {
            int p = c * 32 + lane;
            dt += av[i * 256 + p] * av[j * 256 + p];
        }
        #pragma unroll
        for (int o = 16; o; o >>= 1) dt += __shfl_xor_sync(0xffffffffu, dt, o);
        if (lane == 0) g_sims[bt * 6 + w] = dt * avn[i] * avn[j];
    }
}

// =============================================================
// Kernel C v4: pooled = y @ Wv-slice + bv.
// grid (16 nh, 8 tiles of 16 bt) = 128 CTAs, 512 threads.
// Thread (btq=t&15, jg=(t>>4)&15, ds=t>>8): 4 j's, half the d-range;
// halves combined via smem at the end. Reg-prefetch pipelined.
// =============================================================
__global__ void __launch_bounds__(512, 1)
pooled_kernel(const float* __restrict__ Wv, const float* __restrict__ bv) {
    const int nh = blockIdx.x, btile = blockIdx.y;
    const int n = nh >> 2, h = nh & 3;
    __shared__ __align__(16) float wv_s[64 * 64];   // [d][j] 16KB
    __shared__ __align__(16) float ys[16 * 66];     // [bt][d] padded
    __shared__ __align__(16) float red[256 * 4];    // d-half partials
    const int t = threadIdx.x;
    const int btq = t & 15, jg = (t >> 4) & 15, ds = t >> 8;
    const int bt0 = btile * 16;

    // loaders: wv 1024 float4 / 512 thr = 2; ys 512 float2 / 512 thr = 1
    float4 wr[2]; float2 yr;
    #pragma unroll
    for (int r = 0; r < 2; r++) {
        int li = r * 512 + t, d = li >> 4, c4 = li & 15;
        wr[r] = *(const float4*)(Wv + ((size_t)(n * DV + d)) * DB + h * 64 + c4 * 4);
    }
    yr = *(const float2*)(g_y + ((size_t)(nh * BT + bt0 + (t >> 5))) * DV + (t & 31) * 2);

    u64 acc0 = 0ull, acc1 = 0ull;
    const int dbase = ds * 32;

    for (int kc = 0; kc < 16; kc++) {
        #pragma unroll
        for (int r = 0; r < 2; r++) {
            int li = r * 512 + t, d = li >> 4, c4 = li & 15;
            *(float4*)(wv_s + d * 64 + c4 * 4) = wr[r];
        }
        *(float2*)(ys + (t >> 5) * 66 + (t & 31) * 2) = yr;
        __syncthreads();

        if (kc + 1 < 16) {
            const int kn = kc + 1;
            #pragma unroll
            for (int r = 0; r < 2; r++) {
                int li = r * 512 + t, d = li >> 4, c4 = li & 15;
                wr[r] = *(const float4*)(Wv + ((size_t)(n * DV + kn * 64 + d)) * DB
                                         + h * 64 + c4 * 4);
            }
            yr = *(const float2*)(g_y + ((size_t)(nh * BT + bt0 + (t >> 5))) * DV
                                  + kn * 64 + (t & 31) * 2);
        }

        #pragma unroll 8
        for (int dd = 0; dd < 32; dd++) {
            const int d = dbase + dd;
            u64 y2 = dup2(ys[btq * 66 + d]);
            ulonglong2 w2 = *(const ulonglong2*)(wv_s + d * 64 + jg * 4);
            acc0 = fma2(y2, w2.x, acc0);
            acc1 = fma2(y2, w2.y, acc1);
        }
        __syncthreads();
    }

    // combine d-halves
    if (ds == 1) {
        ((u64*)red)[(t - 256) * 2]     = acc0;
        ((u64*)red)[(t - 256) * 2 + 1] = acc1;
    }
    __syncthreads();
    if (ds == 0) {
        acc0 = add2(acc0, ((const u64*)red)[t * 2]);
        acc1 = add2(acc1, ((const u64*)red)[t * 2 + 1]);
        float a0, a1, a2, a3;
        unpack2(acc0, a0, a1);
        unpack2(acc1, a2, a3);
        const float* bvp = bv + n * DB + h * 64 + jg * 4;
        float4 o = make_float4(a0 + bvp[0], a1 + bvp[1], a2 + bvp[2], a3 + bvp[3]);
        *(float4*)(g_pooled + ((size_t)(n * BT + bt0 + btq)) * DB + h * 64 + jg * 4) = o;
    }
}

// =============================================================
// Kernel D v4: out = pooled @ Wo + bo, transposed write.
// grid (4 n, 32 tiles of 4 bt) = 128 CTAs, 512 threads.
// Thread (btq=t&3, mq=t>>2): 1 bt x 2 m. Reg-prefetch pipelined.
// =============================================================
__global__ void __launch_bounds__(512, 1)
out_kernel(const float* __restrict__ Wo, const float* __restrict__ bo,
           float* __restrict__ out) {
    const int n = blockIdx.x, bt0 = blockIdx.y * 4;
    __shared__ __align__(16) float ps[4 * 260];    // pooled tile, padded
    __shared__ __align__(16) float ws[16 * 256];   // Wo chunk 16KB
    const int t = threadIdx.x;
    const int btq = t & 3, mq = t >> 2;            // m = mq*2

    // load pooled tile once (1024 floats = 512 float2)
    *(float2*)(ps + (t >> 7) * 260 + (t & 127) * 2) =
        *(const float2*)(g_pooled + ((size_t)(n * BT + bt0 + (t >> 7))) * DB + (t & 127) * 2);

    // Wo chunk loader: 1024 float4 / 512 thr = 2
    float4 wr[2];
    #pragma unroll
    for (int r = 0; r < 2; r++) {
        int li = r * 512 + t, kk = li >> 6, c4 = li & 63;
        wr[r] = *(const float4*)(Wo + ((size_t)(n * DB + kk)) * DB + c4 * 4);
    }

    u64 acc = 0ull;

    for (int kc = 0; kc < 16; kc++) {
        #pragma unroll
        for (int r = 0; r < 2; r++) {
            int li = r * 512 + t, kk = li >> 6, c4 = li & 63;
            *(float4*)(ws + kk * 256 + c4 * 4) = wr[r];
        }
        __syncthreads();

        if (kc + 1 < 16) {
            #pragma unroll
            for (int r = 0; r < 2; r++) {
                int li = r * 512 + t, kk = li >> 6, c4 = li & 63;
                wr[r] = *(const float4*)(Wo + ((size_t)(n * DB + (kc + 1) * 16 + kk)) * DB
                                         + c4 * 4);
            }
        }

        #pragma unroll
        for (int k = 0; k < 16; k++) {
            u64 p2 = dup2(ps[btq * 260 + kc * 16 + k]);
            acc = fma2(p2, *(const u64*)(ws + k * 256 + mq * 2), acc);
        }
        __syncthreads();
    }

    float a0, a1;
    unpack2(acc, a0, a1);
    const int m = mq * 2;
    const float* bop = bo + n * DB + m;
    float2 o = make_float2(a0 + bop[0], a1 + bop[1]);
    *(float2*)(out + ((size_t)(bt0 + btq) * 4 + n) * DB + m) = o;
}

// =============================================================
// Kernel E: diversity loss finalize
// =============================================================
__global__ void loss_kernel(float* __restrict__ out) {
    __shared__ float part[6];
    const int t = threadIdx.x;
    if (t < 6) {
        float s = 0.f;
        for (int b = 0; b < BT; b++) s += g_sims[b * 6 + t];
        part[t] = s;
    }
    __syncthreads();
    if (t == 0) {
        float tot = part[0] + part[1] + part[2] + part[3] + part[4] + part[5];
        out[0] = 0.1f * (tot * (1.f / 128.f)) * (1.f / 6.f);
    }
}

// =============================================================
extern "C" void kernel_launch(void* const* d_in, const int* in_sizes, int n_in,
                              void* d_out, int out_size) {
    const float* frame = (const float*)d_in[0];
    const float* gam   = (const float*)d_in[1];
    const float* bet   = (const float*)d_in[2];
    const float* query = (const float*)d_in[3];
    const float* Wk    = (const float*)d_in[4];
    const float* bk    = (const float*)d_in[5];
    const float* Wv    = (const float*)d_in[6];
    const float* bv    = (const float*)d_in[7];
    const float* Wo    = (const float*)d_in[8];
    const float* bo    = (const float*)d_in[9];
    float* out = (float*)d_out;

    prep_kernel<<<16, 256>>>(Wk, query, bk, gam, bet);

    cudaFuncSetAttribute(main_kernel, cudaFuncAttributeMaxDynamicSharedMemorySize,
                         SMEM_MAIN_BYTES);
    main_kernel<<<128, 256, SMEM_MAIN_BYTES>>>(frame, gam, bet);

    pooled_kernel<<<dim3(16, 8), 512>>>(Wv, bv);
    out_kernel<<<dim3(4, 32), 512>>>(Wo, bo, out);

    if (out_size > BT * NBR * DB)
        loss_kernel<<<1, 32>>>(out + (size_t)BT * NBR * DB);
}

// round 6
// speedup vs baseline: 2.9839x; 1.0187x over previous
#include <cuda_runtime.h>
#include <math.h>
#include <stdint.h>

// Problem constants
#define BT   128          // B*T
#define NP   256          // patches
#define DV   1024         // D_VISION
#define NHD  16           // N_BRANCHES * N_HEADS
#define NBR  4
#define DB   256          // D_BRANCH
#define SCALE 0.125f      // HEAD_DIM^-0.5

#define CH    16          // patches per chunk (main kernel)
#define NCH   16          // chunks per bt
#define CHBYTES (CH * DV * 4)   // 65536

typedef unsigned long long u64;

// -------- device scratch (no allocation allowed) --------
__device__ __align__(16) float g_wqg[NHD * DV];
__device__ float g_gw [NHD];
__device__ float g_scb[NHD];
__device__ __align__(16) float g_y[(size_t)NHD * BT * DV];   // 8 MB
__device__ __align__(16) float g_pooled[NBR * BT * DB];
__device__ float g_sims[BT * 6];

// ---------------- f32x2 helpers ----------------
__device__ __forceinline__ u64 fma2(u64 a, u64 b, u64 c) {
    u64 d;
    asm("fma.rn.f32x2 %0, %1, %2, %3;" : "=l"(d) : "l"(a), "l"(b), "l"(c));
    return d;
}
__device__ __forceinline__ u64 mul2(u64 a, u64 b) {
    u64 d;
    asm("mul.rn.f32x2 %0, %1, %2;" : "=l"(d) : "l"(a), "l"(b));
    return d;
}
__device__ __forceinline__ u64 add2(u64 a, u64 b) {
    u64 d;
    asm("add.rn.f32x2 %0, %1, %2;" : "=l"(d) : "l"(a), "l"(b));
    return d;
}
__device__ __forceinline__ u64 dup2(float v) {
    u64 r;
    asm("mov.b64 %0, {%1, %1};" : "=l"(r) : "f"(v));
    return r;
}
__device__ __forceinline__ u64 pack2(float lo, float hi) {
    u64 r;
    asm("mov.b64 %0, {%1, %2};" : "=l"(r) : "f"(lo), "f"(hi));
    return r;
}
__device__ __forceinline__ void unpack2(u64 v, float& lo, float& hi) {
    asm("mov.b64 {%0, %1}, %2;" : "=f"(lo), "=f"(hi) : "l"(v));
}

// ---------------- mbarrier / bulk-copy helpers ----------------
__device__ __forceinline__ uint32_t smem_u32(const void* p) {
    uint32_t a;
    asm("{ .reg .u64 t; cvta.to.shared.u64 t, %1; cvt.u32.u64 %0, t; }"
        : "=r"(a) : "l"(p));
    return a;
}
__device__ __forceinline__ void mbar_init(uint32_t mbar, uint32_t count) {
    asm volatile("mbarrier.init.shared.b64 [%0], %1;" :: "r"(mbar), "r"(count) : "memory");
}
__device__ __forceinline__ void mbar_expect(uint32_t mbar, uint32_t bytes) {
    asm volatile("mbarrier.arrive.expect_tx.shared.b64 _, [%0], %1;"
                 :: "r"(mbar), "r"(bytes) : "memory");
}
__device__ __forceinline__ void mbar_wait(uint32_t mbar, int phase) {
    asm volatile(
        "{\n\t.reg .pred P;\n\t"
        "WL_%=:\n\t"
        "mbarrier.try_wait.parity.acquire.cta.shared::cta.b64 P, [%0], %1, 0x989680;\n\t"
        "@P bra.uni WD_%=;\n\t"
        "bra.uni WL_%=;\n\t"
        "WD_%=:\n\t}"
        :: "r"(mbar), "r"(phase) : "memory");
}
__device__ __forceinline__ void bulk_g2s(uint32_t dst, const void* src,
                                         uint32_t bytes, uint32_t mbar) {
    asm volatile(
        "cp.async.bulk.shared::cluster.global.mbarrier::complete_tx::bytes [%0], [%1], %2, [%3];"
        :: "r"(dst), "l"(src), "r"(bytes), "r"(mbar) : "memory");
}

// =============================================================
// Kernel A: fold query into Wk (+ layernorm affine folding)
// =============================================================
__global__ void prep_kernel(const float* __restrict__ Wk,
                            const float* __restrict__ query,
                            const float* __restrict__ bk,
                            const float* __restrict__ gamma,
                            const float* __restrict__ beta) {
    const int nh = blockIdx.x;
    const int n = nh >> 2, h = nh & 3;
    __shared__ float q_s[64];
    __shared__ float r1[256], r2[256];
    const int t = threadIdx.x;
    if (t < 64) q_s[t] = query[(n * 4 + h) * 64 + t];
    __syncthreads();

    float gw_part = 0.f, bw_part = 0.f;
    const float4* qq = (const float4*)q_s;
    for (int d = t; d < DV; d += 256) {
        const float4* w4 = (const float4*)(Wk + ((size_t)(n * DV + d)) * DB + h * 64);
        float s = 0.f;
        #pragma unroll
        for (int j = 0; j < 16; j++) {
            float4 a = w4[j]; float4 b = qq[j];
            s += a.x * b.x + a.y * b.y + a.z * b.z + a.w * b.w;
        }
        g_wqg[nh * DV + d] = SCALE * gamma[d] * s;
        gw_part += gamma[d] * s;
        bw_part += beta[d] * s;
    }
    r1[t] = gw_part; r2[t] = bw_part;
    __syncthreads();
    for (int s = 128; s; s >>= 1) {
        if (t < s) { r1[t] += r1[t + s]; r2[t] += r2[t + s]; }
        __syncthreads();
    }
    if (t == 0) {
        float bq = 0.f;
        for (int j = 0; j < 64; j++) bq += bk[n * DB + h * 64 + j] * q_s[j];
        g_gw[nh]  = SCALE * r1[0];
        g_scb[nh] = SCALE * (r2[0] + bq);
    }
}

// =============================================================
// Kernel B v5: single-pass main kernel, 256 threads / 8 warps.
//  dots+LN fused: warp w -> 4 rows (rg=w&3), 8 patches (pg=w>>2);
//    LN stats computed by warp rg for its pp==rg patch pair (from regs).
//    Raw dots stored to sc; LN correction applied in softmax phase.
//  softmax: warp w -> rows 2w (lanes 0-15), 2w+1 (lanes 16-31).
//  yacc: thread owns 4 cols; rows packed pairwise into u64 lanes.
//  3 barriers per chunk (was 4).
// =============================================================
#define SMEM_MAIN_FLOATS 38784
#define SMEM_MAIN_BYTES  (SMEM_MAIN_FLOATS * 4)

__global__ void __launch_bounds__(256, 1)
main_kernel(const float* __restrict__ frame,
            const float* __restrict__ gamma,
            const float* __restrict__ beta) {
    extern __shared__ float smf[];
    float* f2s   = smf + 4;     // 16 (u64-pairs per row-pair)
    float* mrow  = smf + 20;
    float* invsr = smf + 36;
    float* ccrow = smf + 52;
    float* avn   = smf + 68;    // 4
    float* mu    = smf + 128;
    float* rsig  = smf + 384;
    float* ar2c  = smf + 640;   // [patch 16][row 16]
    float* av    = smf + 896;
    float* sc    = smf + 1920;  // 16 x 256 scores (raw -> corrected)
    float* buf   = smf + 6016;  // 2 x 16 x 1024

    const int t = threadIdx.x, w = t >> 5, lane = t & 31;
    const int bt = blockIdx.x;
    const uint32_t sbase = smem_u32(smf);
    const uint32_t mbar0 = sbase, mbar1 = sbase + 8;
    const uint32_t bufu = smem_u32(buf);

    const int rg = w & 3, pg = w >> 2;
    const int rbase = rg * 4;

    // persistent folded-query weights for 4 rows (128 regs)
    u64 wR[4][16];
    #pragma unroll
    for (int rr = 0; rr < 4; rr++) {
        const ulonglong2* wp = (const ulonglong2*)(g_wqg + (rbase + rr) * DV);
        #pragma unroll
        for (int c = 0; c < 8; c++) {
            ulonglong2 v = wp[c * 32 + lane];
            wR[rr][2*c] = v.x; wR[rr][2*c+1] = v.y;
        }
    }

    if (t == 0) { mbar_init(mbar0, 1); mbar_init(mbar1, 1); }
    __syncthreads();

    const char* src = (const char*)(frame + (size_t)bt * NP * DV);
    if (t == 0) {
        mbar_expect(mbar0, CHBYTES);
        bulk_g2s(bufu, src, CHBYTES, mbar0);
        mbar_expect(mbar1, CHBYTES);
        bulk_g2s(bufu + CHBYTES, src + CHBYTES, CHBYTES, mbar1);
    }

    // yacc: thread owns cols 4t..4t+3; rows packed pairwise (8 pairs)
    u64 yacc[8][4];
    #pragma unroll
    for (int q = 0; q < 8; q++)
        #pragma unroll
        for (int c = 0; c < 4; c++) yacc[q][c] = 0ull;

    // softmax state: lanes 0-15 -> row 2w, lanes 16-31 -> row 2w+1
    const int half = lane >> 4, srow = 2 * w + half, pl = lane & 15;
    const float gwS = g_gw[srow], sbS = g_scb[srow];
    float mO = -1e30f, sO = 0.f, cpO = 0.f;

    for (int kc = 0; kc < NCH; kc++) {
        const int b = kc & 1;
        const uint32_t mb = b ? mbar1 : mbar0;
        mbar_wait(mb, (kc >> 1) & 1);
        float* xb = buf + b * (CH * DV);

        // ---- dots + fused LN stats ----
        {
            const ulonglong2* x2 = (const ulonglong2*)xb;
            const bool b16 = (lane & 16) != 0;
            const bool b8  = (lane & 8)  != 0;
            const bool b4  = (lane & 4)  != 0;
            #pragma unroll
            for (int pp = 0; pp < 4; pp++) {
                const int p0 = pg * 8 + 2 * pp, p1 = p0 + 1;
                const ulonglong2* r0 = x2 + p0 * 256;
                const ulonglong2* r1 = x2 + p1 * 256;
                const bool doStats = (pp == rg);
                u64 a[8];
                #pragma unroll
                for (int i = 0; i < 8; i++) a[i] = 0ull;
                float s0 = 0.f, ss0 = 0.f, s1 = 0.f, ss1 = 0.f;
                #pragma unroll
                for (int c = 0; c < 8; c++) {
                    ulonglong2 x0 = r0[c * 32 + lane];
                    ulonglong2 x1 = r1[c * 32 + lane];
                    if (doStats) {
                        float f0, f1, f2, f3;
                        unpack2(x0.x, f0, f1); unpack2(x0.y, f2, f3);
                        s0  += (f0 + f1) + (f2 + f3);
                        ss0 += f0*f0 + f1*f1 + f2*f2 + f3*f3;
                        unpack2(x1.x, f0, f1); unpack2(x1.y, f2, f3);
                        s1  += (f0 + f1) + (f2 + f3);
                        ss1 += f0*f0 + f1*f1 + f2*f2 + f3*f3;
                    }
                    #pragma unroll
                    for (int rr = 0; rr < 4; rr++) {
                        a[2*rr]   = fma2(x0.x, wR[rr][2*c],   a[2*rr]);
                        a[2*rr]   = fma2(x0.y, wR[rr][2*c+1], a[2*rr]);
                        a[2*rr+1] = fma2(x1.x, wR[rr][2*c],   a[2*rr+1]);
                        a[2*rr+1] = fma2(x1.y, wR[rr][2*c+1], a[2*rr+1]);
                    }
                }
                if (doStats) {
                    #pragma unroll
                    for (int o = 16; o; o >>= 1) {
                        s0  += __shfl_xor_sync(0xffffffffu, s0,  o);
                        ss0 += __shfl_xor_sync(0xffffffffu, ss0, o);
                        s1  += __shfl_xor_sync(0xffffffffu, s1,  o);
                        ss1 += __shfl_xor_sync(0xffffffffu, ss1, o);
                    }
                    if (lane == 0) {
                        float m0v = s0 * (1.f / 1024.f);
                        mu[kc * CH + p0] = m0v;
                        rsig[kc * CH + p0] = rsqrtf(ss0 * (1.f / 1024.f) - m0v * m0v + 1e-5f);
                        float m1v = s1 * (1.f / 1024.f);
                        mu[kc * CH + p1] = m1v;
                        rsig[kc * CH + p1] = rsqrtf(ss1 * (1.f / 1024.f) - m1v * m1v + 1e-5f);
                    }
                }
                float v[8];
                #pragma unroll
                for (int i = 0; i < 8; i++) {
                    float lo, hi;
                    unpack2(a[i], lo, hi);
                    v[i] = lo + hi;
                }
                // packed tree: 8 dots -> distributed lanes in 9 shuffles
                float u2[4];
                #pragma unroll
                for (int i = 0; i < 4; i++) {
                    float xx = b16 ? v[2*i] : v[2*i+1];
                    float tt = __shfl_xor_sync(0xffffffffu, xx, 16);
                    u2[i] = (b16 ? v[2*i+1] : v[2*i]) + tt;
                }
                float q2[2];
                #pragma unroll
                for (int i = 0; i < 2; i++) {
                    float xx = b8 ? u2[2*i] : u2[2*i+1];
                    float tt = __shfl_xor_sync(0xffffffffu, xx, 8);
                    q2[i] = (b8 ? u2[2*i+1] : u2[2*i]) + tt;
                }
                float z;
                {
                    float xx = b4 ? q2[0] : q2[1];
                    float tt = __shfl_xor_sync(0xffffffffu, xx, 4);
                    z = (b4 ? q2[1] : q2[0]) + tt;
                }
                z += __shfl_xor_sync(0xffffffffu, z, 2);
                z += __shfl_xor_sync(0xffffffffu, z, 1);
                if ((lane & 3) == 0) {
                    int idx = ((lane >> 4) & 1) | ((lane >> 2) & 2) | (lane & 4);
                    int rr = idx >> 1, px = idx & 1;
                    int p = p0 + px;
                    int row = rbase + rr;
                    sc[row * 256 + kc * CH + p] = z;    // RAW dot
                }
            }
        }
        __syncthreads();

        // ---- online softmax (applies LN correction to raw dot) ----
        {
            float raw = sc[srow * 256 + kc * CH + pl];
            float rs = rsig[kc * CH + pl], mv = mu[kc * CH + pl];
            float vv = fmaf(rs, raw, fmaf(-(rs * mv), gwS, sbS));
            sc[srow * 256 + kc * CH + pl] = vv;        // corrected (for diversity)
            float c = vv;
            #pragma unroll
            for (int o = 8; o; o >>= 1)
                c = fmaxf(c, __shfl_xor_sync(0xffffffffu, c, o));
            float mn = fmaxf(mO, c);
            float f = __expf(mO - mn);
            float e = __expf(vv - mn);
            float ar = e * rs;
            float su = e, cq = ar * mv;
            #pragma unroll
            for (int o = 8; o; o >>= 1) {
                su += __shfl_xor_sync(0xffffffffu, su, o);
                cq += __shfl_xor_sync(0xffffffffu, cq, o);
            }
            sO = sO * f + su;
            cpO = cpO * f + cq;
            mO = mn;
            ar2c[pl * 16 + srow] = ar;
            if (pl == 0) f2s[srow] = f;
        }
        __syncthreads();

        // ---- yacc rescale + accumulate (4 cols/thread) ----
        {
            #pragma unroll
            for (int q = 0; q < 8; q++) {
                u64 f2 = ((const u64*)f2s)[q];
                #pragma unroll
                for (int c = 0; c < 4; c++) yacc[q][c] = mul2(yacc[q][c], f2);
            }
            const float4* xs4 = (const float4*)xb;
            #pragma unroll 2
            for (int lp = 0; lp < CH; lp++) {
                float4 xv = xs4[lp * 256 + t];
                u64 xd0 = dup2(xv.x), xd1 = dup2(xv.y);
                u64 xd2 = dup2(xv.z), xd3 = dup2(xv.w);
                const ulonglong2* arp = (const ulonglong2*)(ar2c + lp * 16);
                #pragma unroll
                for (int qq = 0; qq < 4; qq++) {
                    ulonglong2 a2 = arp[qq];
                    yacc[2*qq][0]   = fma2(a2.x, xd0, yacc[2*qq][0]);
                    yacc[2*qq][1]   = fma2(a2.x, xd1, yacc[2*qq][1]);
                    yacc[2*qq][2]   = fma2(a2.x, xd2, yacc[2*qq][2]);
                    yacc[2*qq][3]   = fma2(a2.x, xd3, yacc[2*qq][3]);
                    yacc[2*qq+1][0] = fma2(a2.y, xd0, yacc[2*qq+1][0]);
                    yacc[2*qq+1][1] = fma2(a2.y, xd1, yacc[2*qq+1][1]);
                    yacc[2*qq+1][2] = fma2(a2.y, xd2, yacc[2*qq+1][2]);
                    yacc[2*qq+1][3] = fma2(a2.y, xd3, yacc[2*qq+1][3]);
                }
            }
        }
        __syncthreads();   // buffer b free

        if (t == 0 && kc + 2 < NCH) {
            mbar_expect(mb, CHBYTES);
            bulk_g2s(bufu + b * CHBYTES, src + (size_t)(kc + 2) * CHBYTES, CHBYTES, mb);
        }
    }

    // ---- finalize per-row softmax state (lanes 0 and 16 of each warp) ----
    if (pl == 0) {
        float is = 1.f / sO;
        invsr[srow] = is;
        ccrow[srow] = cpO * is;
        mrow[srow]  = mO;
    }
    __syncthreads();

    // ---- epilogue: y = gamma*(yacc/s - cc) + beta -> g_y (4 cols/thread) ----
    {
        float4 g4 = ((const float4*)gamma)[t];
        float4 b4 = ((const float4*)beta)[t];
        u64 gd[4] = { dup2(g4.x), dup2(g4.y), dup2(g4.z), dup2(g4.w) };
        u64 bd[4] = { dup2(b4.x), dup2(b4.y), dup2(b4.z), dup2(b4.w) };
        #pragma unroll
        for (int q = 0; q < 8; q++) {
            u64 is2 = pack2(invsr[2*q], invsr[2*q+1]);
            u64 nc2 = pack2(-ccrow[2*q], -ccrow[2*q+1]);
            float lo[4], hi[4];
            #pragma unroll
            for (int c = 0; c < 4; c++) {
                u64 o = fma2(fma2(yacc[q][c], is2, nc2), gd[c], bd[c]);
                unpack2(o, lo[c], hi[c]);
            }
            ((float4*)(g_y + (size_t)((2*q)     * BT + bt) * DV))[t] =
                make_float4(lo[0], lo[1], lo[2], lo[3]);
            ((float4*)(g_y + (size_t)((2*q + 1) * BT + bt) * DV))[t] =
                make_float4(hi[0], hi[1], hi[2], hi[3]);
        }
    }

    // ---- diversity partials (recompute attn from corrected scores) ----
    if (w < 4) {
        const int n = w;
        float nrm = 0.f;
        #pragma unroll
        for (int i = 0; i < 8; i++) {
            int p = i * 32 + lane;
            float aa = 0.f;
            #pragma unroll
            for (int h = 0; h < 4; h++) {
                int r = 4 * n + h;
                aa += __expf(sc[r * 256 + p] - mrow[r]) * invsr[r];
            }
            aa *= 0.25f;
            av[n * 256 + p] = aa;
            nrm += aa * aa;
        }
        #pragma unroll
        for (int o = 16; o; o >>= 1) nrm += __shfl_xor_sync(0xffffffffu, nrm, o);
        if (lane == 0) avn[n] = 1.f / fmaxf(sqrtf(nrm), 1e-8f);
    }
    __syncthreads();
    if (w < 6) {
        const int pi[6] = {0, 0, 0, 1, 1, 2};
        const int pj[6] = {1, 2, 3, 2, 3, 3};
        int i = pi[w], j = pj[w];
        float dt = 0.f;
        #pragma unroll
        for (int c = 0; c < 8; c++) {
            int p = c * 32 + lane;
            dt += av[i * 256 + p] * av[j * 256 + p];
        }
        #pragma unroll
        for (int o = 16; o; o >>= 1) dt += __shfl_xor_sync(0xffffffffu, dt, o);
        if (lane == 0) g_sims[bt * 6 + w] = dt * avn[i] * avn[j];
    }
}

// =============================================================
// Kernel C v5: pooled = y @ Wv-slice + bv.
// grid (16 nh, 8 tiles of 16 bt) = 128 CTAs, 512 threads.
// Double-buffered smem + 2-chunk-deep register prefetch; 1 sync/chunk.
// =============================================================
__global__ void __launch_bounds__(512, 1)
pooled_kernel(const float* __restrict__ Wv, const float* __restrict__ bv) {
    const int nh = blockIdx.x, btile = blockIdx.y;
    const int n = nh >> 2, h = nh & 3;
    __shared__ __align__(16) float wv_s[2][64 * 64];   // [d][j] 2x16KB
    __shared__ __align__(16) float ys[2][16 * 66];     // [bt][d] padded
    __shared__ __align__(16) float red[256 * 4];       // d-half partials
    const int t = threadIdx.x;
    const int btq = t & 15, jg = (t >> 4) & 15, ds = t >> 8;
    const int bt0 = btile * 16;
    const int dbase = ds * 32;

    const int wli_d0 = t >> 4, wli_c4 = t & 15;         // +512: d += 32
    const int yb = t >> 5, yc = t & 31;

    float4 wr[2]; float2 yr;
    #define P_LOAD(KC) do { \
        wr[0] = *(const float4*)(Wv + ((size_t)(n * DV + (KC) * 64 + wli_d0)) * DB + h * 64 + wli_c4 * 4); \
        wr[1] = *(const float4*)(Wv + ((size_t)(n * DV + (KC) * 64 + wli_d0 + 32)) * DB + h * 64 + wli_c4 * 4); \
        yr = *(const float2*)(g_y + ((size_t)(nh * BT + bt0 + yb)) * DV + (KC) * 64 + yc * 2); \
    } while (0)
    #define P_STORE(B) do { \
        *(float4*)(wv_s[B] + wli_d0 * 64 + wli_c4 * 4) = wr[0]; \
        *(float4*)(wv_s[B] + (wli_d0 + 32) * 64 + wli_c4 * 4) = wr[1]; \
        *(float2*)(ys[B] + yb * 66 + yc * 2) = yr; \
    } while (0)

    P_LOAD(0); P_STORE(0); P_LOAD(1);
    __syncthreads();

    u64 acc0 = 0ull, acc1 = 0ull;

    for (int kc = 0; kc < 16; kc++) {
        const int cb = kc & 1;
        if (kc + 1 < 16) P_STORE((kc + 1) & 1);
        if (kc + 2 < 16) P_LOAD(kc + 2);

        const float* ysb = ys[cb] + btq * 66;
        const float* wvb = wv_s[cb];
        #pragma unroll 8
        for (int dd = 0; dd < 32; dd++) {
            const int d = dbase + dd;
            u64 y2 = dup2(ysb[d]);
            ulonglong2 w2 = *(const ulonglong2*)(wvb + d * 64 + jg * 4);
            acc0 = fma2(y2, w2.x, acc0);
            acc1 = fma2(y2, w2.y, acc1);
        }
        __syncthreads();
    }
    #undef P_LOAD
    #undef P_STORE

    // combine d-halves
    if (ds == 1) {
        ((u64*)red)[(t - 256) * 2]     = acc0;
        ((u64*)red)[(t - 256) * 2 + 1] = acc1;
    }
    __syncthreads();
    if (ds == 0) {
        acc0 = add2(acc0, ((const u64*)red)[t * 2]);
        acc1 = add2(acc1, ((const u64*)red)[t * 2 + 1]);
        float a0, a1, a2, a3;
        unpack2(acc0, a0, a1);
        unpack2(acc1, a2, a3);
        const float* bvp = bv + n * DB + h * 64 + jg * 4;
        float4 o = make_float4(a0 + bvp[0], a1 + bvp[1], a2 + bvp[2], a3 + bvp[3]);
        *(float4*)(g_pooled + ((size_t)(n * BT + bt0 + btq)) * DB + h * 64 + jg * 4) = o;
    }
}

// =============================================================
// Kernel D v5: out = pooled @ Wo + bo, transposed write.
// grid (4 n, 32 tiles of 4 bt) = 128 CTAs, 512 threads.
// Double-buffered smem + 2-deep prefetch; split accumulator.
// =============================================================
__global__ void __launch_bounds__(512, 1)
out_kernel(const float* __restrict__ Wo, const float* __restrict__ bo,
           float* __restrict__ out) {
    const int n = blockIdx.x, bt0 = blockIdx.y * 4;
    __shared__ __align__(16) float ps[4 * 260];
    __shared__ __align__(16) float ws[2][16 * 256];   // 2x16KB
    const int t = threadIdx.x;
    const int btq = t & 3, mq = t >> 2;               // m = mq*2

    // load pooled tile once
    *(float2*)(ps + (t >> 7) * 260 + (t & 127) * 2) =
        *(const float2*)(g_pooled + ((size_t)(n * BT + bt0 + (t >> 7))) * DB + (t & 127) * 2);

    const int wk0 = t >> 6, wc4 = t & 63;             // +512: k += 8
    float4 wr[2];
    #define O_LOAD(KC) do { \
        wr[0] = *(const float4*)(Wo + ((size_t)(n * DB + (KC) * 16 + wk0)) * DB + wc4 * 4); \
        wr[1] = *(const float4*)(Wo + ((size_t)(n * DB + (KC) * 16 + wk0 + 8)) * DB + wc4 * 4); \
    } while (0)
    #define O_STORE(B) do { \
        *(float4*)(ws[B] + wk0 * 256 + wc4 * 4) = wr[0]; \
        *(float4*)(ws[B] + (wk0 + 8) * 256 + wc4 * 4) = wr[1]; \
    } while (0)

    O_LOAD(0); O_STORE(0); O_LOAD(1);
    __syncthreads();

    u64 accA = 0ull, accB = 0ull;

    for (int kc = 0; kc < 16; kc++) {
        const int cb = kc & 1;
        if (kc + 1 < 16) O_STORE((kc + 1) & 1);
        if (kc + 2 < 16) O_LOAD(kc + 2);

        const float* psb = ps + btq * 260 + kc * 16;
        const float* wsb = ws[cb];
        #pragma unroll
        for (int k = 0; k < 16; k += 2) {
            u64 pA = dup2(psb[k]);
            u64 pB = dup2(psb[k + 1]);
            accA = fma2(pA, *(const u64*)(wsb + k * 256 + mq * 2), accA);
            accB = fma2(pB, *(const u64*)(wsb + (k + 1) * 256 + mq * 2), accB);
        }
        __syncthreads();
    }
    #undef O_LOAD
    #undef O_STORE

    u64 acc = add2(accA, accB);
    float a0, a1;
    unpack2(acc, a0, a1);
    const int m = mq * 2;
    const float* bop = bo + n * DB + m;
    float2 o = make_float2(a0 + bop[0], a1 + bop[1]);
    *(float2*)(out + ((size_t)(bt0 + btq) * 4 + n) * DB + m) = o;
}

// =============================================================
// Kernel E: diversity loss finalize
// =============================================================
__global__ void loss_kernel(float* __restrict__ out) {
    __shared__ float part[6];
    const int t = threadIdx.x;
    if (t < 6) {
        float s = 0.f;
        for (int b = 0; b < BT; b++) s += g_sims[b * 6 + t];
        part[t] = s;
    }
    __syncthreads();
    if (t == 0) {
        float tot = part[0] + part[1] + part[2] + part[3] + part[4] + part[5];
        out[0] = 0.1f * (tot * (1.f / 128.f)) * (1.f / 6.f);
    }
}

// =============================================================
extern "C" void kernel_launch(void* const* d_in, const int* in_sizes, int n_in,
                              void* d_out, int out_size) {
    const float* frame = (const float*)d_in[0];
    const float* gam   = (const float*)d_in[1];
    const float* bet   = (const float*)d_in[2];
    const float* query = (const float*)d_in[3];
    const float* Wk    = (const float*)d_in[4];
    const float* bk    = (const float*)d_in[5];
    const float* Wv    = (const float*)d_in[6];
    const float* bv    = (const float*)d_in[7];
    const float* Wo    = (const float*)d_in[8];
    const float* bo    = (const float*)d_in[9];
    float* out = (float*)d_out;

    prep_kernel<<<16, 256>>>(Wk, query, bk, gam, bet);

    cudaFuncSetAttribute(main_kernel, cudaFuncAttributeMaxDynamicSharedMemorySize,
                         SMEM_MAIN_BYTES);
    main_kernel<<<128, 256, SMEM_MAIN_BYTES>>>(frame, gam, bet);

    pooled_kernel<<<dim3(16, 8), 512>>>(Wv, bv);
    out_kernel<<<dim3(4, 32), 512>>>(Wo, bo, out);

    if (out_size > BT * NBR * DB)
        loss_kernel<<<1, 32>>>(out + (size_t)BT * NBR * DB);
}